// round 2
// baseline (speedup 1.0000x reference)
#include <cuda_runtime.h>
#include <math.h>

#define BATCH 256
#define SEQ 199
#define LSEQ 200          // S+1
#define EMB 512
#define HID 512
#define G4H 2048          // 4*H
#define NLAY 5
#define NFC1 512
#define NFC2 256
#define SIGMA_MIX 0.5f

#define NBLK_LSTM 128
#define SMEM_LSTM ((512 * 64 + 16 * 64) * 4)   // Whh slice + A tile = 132 KB

// ---------------------------------------------------------------------------
// Static device scratch (allocation-free rule: __device__ globals only)
// ---------------------------------------------------------------------------
__device__ float d_qa  [(size_t)LSEQ*BATCH*HID];   // qa embeddings, time-major [L,B,H]
__device__ float d_qemb[(size_t)LSEQ*BATCH*HID];   // q_embed (no response emb)
__device__ float d_x0  [(size_t)LSEQ*BATCH*HID];   // LSTM ping
__device__ float d_x1  [(size_t)LSEQ*BATCH*HID];   // LSTM pong
__device__ float d_gx  [(size_t)LSEQ*BATCH*G4H];   // input-projection gates (all t)
__device__ float d_t0  [(size_t)LSEQ*BATCH*HID];   // GCN feature-gemm out
__device__ float d_g0  [(size_t)LSEQ*BATCH*HID];   // GCN ping
__device__ float d_g1  [(size_t)LSEQ*BATCH*HID];   // GCN pong
__device__ float d_xcat[(size_t)BATCH*SEQ*(2*EMB)];
__device__ float d_m1  [(size_t)BATCH*SEQ*NFC1];
__device__ float d_m2  [(size_t)BATCH*SEQ*NFC2];
__device__ float d_WgT [(size_t)NLAY*HID*HID];
__device__ float d_W1T [(size_t)NFC1*(2*EMB)];
__device__ float d_W2T [(size_t)NFC2*NFC1];
__device__ float d_bsum[(size_t)NLAY*G4H];
__device__ unsigned d_gbar;

__device__ __forceinline__ float sigf(float x) { return 1.0f / (1.0f + expf(-x)); }

// ---------------------------------------------------------------------------
// NT GEMM:  C[M,N] = act( blend(A,A2)[M,K] @ Bw[N,K]^T + bias )
// ---------------------------------------------------------------------------
template<int BM, int BN, int TM, int TN>
__launch_bounds__(256)
__global__ void gemm_nt(const float* __restrict__ A, const float* __restrict__ A2,
                        float alphaA, float betaA, int lda,
                        const float* __restrict__ Bw, int ldb,
                        float* __restrict__ C, int ldc, int K,
                        const float* __restrict__ bias, int relu)
{
    constexpr int BK = 16;
    __shared__ float As[BK][BM];
    __shared__ float Bs[BK][BN];
    const int tid = threadIdx.x;
    const long bm = (long)blockIdx.y * BM;
    const long bn = (long)blockIdx.x * BN;
    constexpr int TX = BN / TN;
    const int tx = tid % TX;
    const int ty = tid / TX;

    float acc[TM][TN];
#pragma unroll
    for (int i = 0; i < TM; i++)
#pragma unroll
        for (int j = 0; j < TN; j++) acc[i][j] = 0.0f;

    const int lrow = tid >> 2;
    const int lkq  = (tid & 3) * 4;

    for (int k0 = 0; k0 < K; k0 += BK) {
#pragma unroll
        for (int p = 0; p < BM / 64; p++) {
            const int r = p * 64 + lrow;
            const long off = (bm + r) * (long)lda + k0 + lkq;
            float4 v = *reinterpret_cast<const float4*>(&A[off]);
            if (A2) {
                const float4 v2 = *reinterpret_cast<const float4*>(&A2[off]);
                v.x = alphaA * v.x + betaA * v2.x;
                v.y = alphaA * v.y + betaA * v2.y;
                v.z = alphaA * v.z + betaA * v2.z;
                v.w = alphaA * v.w + betaA * v2.w;
            }
            As[lkq + 0][r] = v.x; As[lkq + 1][r] = v.y;
            As[lkq + 2][r] = v.z; As[lkq + 3][r] = v.w;
        }
#pragma unroll
        for (int p = 0; p < BN / 64; p++) {
            const int r = p * 64 + lrow;
            const long off = (bn + r) * (long)ldb + k0 + lkq;
            const float4 v = *reinterpret_cast<const float4*>(&Bw[off]);
            Bs[lkq + 0][r] = v.x; Bs[lkq + 1][r] = v.y;
            Bs[lkq + 2][r] = v.z; Bs[lkq + 3][r] = v.w;
        }
        __syncthreads();
#pragma unroll
        for (int kk = 0; kk < BK; kk++) {
            float a[TM], b[TN];
#pragma unroll
            for (int i = 0; i < TM; i++) a[i] = As[kk][ty * TM + i];
#pragma unroll
            for (int j = 0; j < TN; j++) b[j] = Bs[kk][tx * TN + j];
#pragma unroll
            for (int i = 0; i < TM; i++)
#pragma unroll
                for (int j = 0; j < TN; j++)
                    acc[i][j] = fmaf(a[i], b[j], acc[i][j]);
        }
        __syncthreads();
    }
#pragma unroll
    for (int i = 0; i < TM; i++) {
        const long row = bm + ty * TM + i;
#pragma unroll
        for (int j = 0; j < TN; j++) {
            const long col = bn + tx * TN + j;
            float v = acc[i][j];
            if (bias) v += bias[col];
            if (relu) v = fmaxf(v, 0.0f);
            C[row * (long)ldc + col] = v;
        }
    }
}

// ---------------------------------------------------------------------------
// Persistent LSTM layer: one launch covers all 200 timesteps.
// Grid = 128 blocks (all co-resident on 148 SMs) x 256 threads.
// Block (bq, bc): batch rows [bq*64, bq*64+64), hidden cols [bc*16, bc*16+16).
// Gate-interleaved Whh column mapping: smem col n  <->  Whh row (n%4)*512 + c0 + n/4,
// so each thread owns all 4 gates of one hidden column for 4 batch rows ->
// the LSTM pointwise update fuses into the GEMM epilogue; c-state in registers.
// One software grid barrier per timestep.
// ---------------------------------------------------------------------------
__global__ __launch_bounds__(256)
void lstm_layer_k(const float* __restrict__ gx,   // [LSEQ*BATCH, 4H] (x-proj + bias)
                  const float* __restrict__ Whh,  // [4H, H]
                  float* __restrict__ out)        // [LSEQ*BATCH, H] (doubles as h state)
{
    extern __shared__ float smem[];
    float* Bsw = smem;                               // [512][64] flat: k*64 + n
    float (*As)[64] = (float(*)[64])(smem + 512 * 64); // [16][64]

    const int tid = threadIdx.x;
    const int tx = tid & 15;         // hidden-col within block
    const int ty = tid >> 4;         // batch group (x4 rows)
    const int bm = (blockIdx.x & 3) * 64;       // batch offset
    const int c0 = (blockIdx.x >> 2) * 16;      // hidden-col offset

    // ---- cache this block's Whh slice in smem (once per layer) ----
    for (int i = tid; i < 64 * 128; i += 256) {
        const int n  = i >> 7;               // 0..63 (smem col)
        const int kq = (i & 127) << 2;       // 0..508
        const int row = ((n & 3) << 9) + c0 + (n >> 2);
        const float4 v = *reinterpret_cast<const float4*>(&Whh[(size_t)row * HID + kq]);
        Bsw[(kq + 0) * 64 + n] = v.x;
        Bsw[(kq + 1) * 64 + n] = v.y;
        Bsw[(kq + 2) * 64 + n] = v.z;
        Bsw[(kq + 3) * 64 + n] = v.w;
    }
    __syncthreads();

    float creg[4] = {0.0f, 0.0f, 0.0f, 0.0f};
    const int lrow = tid >> 2;           // 0..63
    const int lkq  = (tid & 3) << 2;     // 0,4,8,12
    unsigned phase = 0;

    for (int t = 0; t < LSEQ; t++) {
        float acc[4][4] = {};
        if (t > 0) {
            const float* h = out + (size_t)(t - 1) * BATCH * HID;
            for (int k0 = 0; k0 < HID; k0 += 16) {
                const float4 v = __ldcg(reinterpret_cast<const float4*>(
                    &h[(size_t)(bm + lrow) * HID + k0 + lkq]));
                As[lkq + 0][lrow] = v.x;
                As[lkq + 1][lrow] = v.y;
                As[lkq + 2][lrow] = v.z;
                As[lkq + 3][lrow] = v.w;
                __syncthreads();
#pragma unroll
                for (int kk = 0; kk < 16; kk++) {
                    float a[4], b[4];
                    *(float4*)a = *(const float4*)&As[kk][ty * 4];
                    *(float4*)b = *(const float4*)&Bsw[(k0 + kk) * 64 + tx * 4];
#pragma unroll
                    for (int i = 0; i < 4; i++)
#pragma unroll
                        for (int j = 0; j < 4; j++)
                            acc[i][j] = fmaf(a[i], b[j], acc[i][j]);
                }
                __syncthreads();
            }
        }
        // ---- fused LSTM pointwise (gate order i,f,g,o) ----
#pragma unroll
        for (int i = 0; i < 4; i++) {
            const int b = bm + ty * 4 + i;
            const size_t gxo = ((size_t)t * BATCH + b) * G4H + c0 + tx;
            const float gi = gx[gxo]            + acc[i][0];
            const float gf = gx[gxo + HID]      + acc[i][1];
            const float gg = gx[gxo + 2 * HID]  + acc[i][2];
            const float go = gx[gxo + 3 * HID]  + acc[i][3];
            const float cv = sigf(gf) * creg[i] + sigf(gi) * tanhf(gg);
            const float hv = sigf(go) * tanhf(cv);
            creg[i] = cv;
            out[((size_t)t * BATCH + b) * HID + c0 + tx] = hv;
        }
        // ---- software grid barrier ----
        __syncthreads();
        if (tid == 0) {
            __threadfence();
            phase++;
            atomicAdd(&d_gbar, 1u);
            while (*(volatile unsigned*)&d_gbar < phase * (unsigned)NBLK_LSTM) {}
            __threadfence();
        }
        __syncthreads();
    }
}

// ---------------------------------------------------------------------------
// Adjacency contraction: C[l, n] = act( sum_k adj[l,k] * T[k,n] )
// ---------------------------------------------------------------------------
__launch_bounds__(256)
__global__ void adj_gemm(const float* __restrict__ adj, const float* __restrict__ T,
                         float* __restrict__ C, int relu)
{
    constexpr int RB = 25;
    constexpr int N = BATCH * HID;
    __shared__ float as[RB][LSEQ];
    const int r0 = blockIdx.y * RB;
    const int n  = blockIdx.x * 256 + threadIdx.x;

    for (int i = threadIdx.x; i < RB * LSEQ; i += 256)
        as[i / LSEQ][i % LSEQ] = adj[(size_t)(r0 + i / LSEQ) * LSEQ + (i % LSEQ)];
    __syncthreads();

    float acc[RB];
#pragma unroll
    for (int r = 0; r < RB; r++) acc[r] = 0.0f;

    for (int k = 0; k < LSEQ; k++) {
        const float t = T[(size_t)k * N + n];
#pragma unroll
        for (int r = 0; r < RB; r++) acc[r] = fmaf(as[r][k], t, acc[r]);
    }
#pragma unroll
    for (int r = 0; r < RB; r++) {
        float v = acc[r];
        if (relu) v = fmaxf(v, 0.0f);
        C[(size_t)(r0 + r) * N + n] = v;
    }
}

// ---------------------------------------------------------------------------
// Embedding gather
// ---------------------------------------------------------------------------
__global__ void embed_k(const int* __restrict__ q, const int* __restrict__ c,
                        const int* __restrict__ r, const int* __restrict__ qsh,
                        const int* __restrict__ csh, const int* __restrict__ rsh,
                        const float* __restrict__ Wq, const float* __restrict__ Wc,
                        const float* __restrict__ Wr,
                        float* __restrict__ qa, float* __restrict__ qemb)
{
    const long idx = (long)blockIdx.x * blockDim.x + threadIdx.x;
    if (idx >= (long)LSEQ * BATCH * HID) return;
    const int e = (int)(idx % HID);
    const int b = (int)((idx / HID) % BATCH);
    const int t = (int)(idx / ((long)HID * BATCH));
    const int pid = (t == 0) ? q[b * SEQ]  : qsh[b * SEQ + t - 1];
    const int cid = (t == 0) ? c[b * SEQ]  : csh[b * SEQ + t - 1];
    const int tgt = (t == 0) ? r[b * SEQ]  : rsh[b * SEQ + t - 1];
    const float qe = Wq[(size_t)pid * EMB + e] + Wc[(size_t)cid * EMB + e];
    qemb[idx] = qe;
    qa[idx]   = qe + Wr[(size_t)tgt * EMB + e];
}

// ---------------------------------------------------------------------------
// Misc small kernels
// ---------------------------------------------------------------------------
__global__ void transpose_k(const float* __restrict__ in, float* __restrict__ out,
                            int R, int Ccols)
{
    __shared__ float tile[32][33];
    int x = blockIdx.x * 32 + threadIdx.x;
    int y = blockIdx.y * 32 + threadIdx.y;
    if (x < Ccols && y < R) tile[threadIdx.y][threadIdx.x] = in[(size_t)y * Ccols + x];
    __syncthreads();
    x = blockIdx.y * 32 + threadIdx.x;
    y = blockIdx.x * 32 + threadIdx.y;
    if (x < R && y < Ccols) out[(size_t)y * R + x] = tile[threadIdx.x][threadIdx.y];
}

__global__ void bsum_k(const float* __restrict__ bih, const float* __restrict__ bhh,
                       float* __restrict__ bsum)
{
    const int i = blockIdx.x * blockDim.x + threadIdx.x;
    if (i < NLAY * G4H) bsum[i] = bih[i] + bhh[i];
}

__global__ void concat_k(const float* __restrict__ hg, const float* __restrict__ qe,
                         float* __restrict__ xcat)
{
    const long idx = (long)blockIdx.x * blockDim.x + threadIdx.x;
    if (idx >= (long)BATCH * SEQ * (2 * EMB)) return;
    const int f = (int)(idx % (2 * EMB));
    const int s = (int)((idx / (2 * EMB)) % SEQ);
    const int b = (int)(idx / ((long)(2 * EMB) * SEQ));
    const size_t src = ((size_t)(s + 1) * BATCH + b) * HID;
    xcat[idx] = (f < EMB) ? hg[src + f] : qe[src + (f - EMB)];
}

__global__ void mlp3_k(const float* __restrict__ X, const float* __restrict__ W3,
                       const float* __restrict__ b3, float* __restrict__ y, int M)
{
    const int warp = (blockIdx.x * blockDim.x + threadIdx.x) >> 5;
    const int lane = threadIdx.x & 31;
    if (warp >= M) return;
    const float* xr = X + (size_t)warp * NFC2;
    float s = 0.0f;
#pragma unroll
    for (int k = lane; k < NFC2; k += 32) s = fmaf(xr[k], W3[k], s);
#pragma unroll
    for (int o = 16; o > 0; o >>= 1) s += __shfl_down_sync(0xffffffffu, s, o);
    if (lane == 0) y[warp] = 1.0f / (1.0f + expf(-(s + b3[0])));
}

// ---------------------------------------------------------------------------
// Orchestration (~32 graph nodes total)
// ---------------------------------------------------------------------------
extern "C" void kernel_launch(void* const* d_in, const int* in_sizes, int n_in,
                              void* d_out, int out_size)
{
    const int   *q   = (const int*)d_in[0],  *c   = (const int*)d_in[1];
    const int   *r   = (const int*)d_in[2],  *qsh = (const int*)d_in[3];
    const int   *csh = (const int*)d_in[4],  *rsh = (const int*)d_in[5];
    const float *adj = (const float*)d_in[6];
    const float *Wq  = (const float*)d_in[7], *Wc  = (const float*)d_in[8];
    const float *Wr  = (const float*)d_in[9];
    const float *Wih = (const float*)d_in[10], *Whh = (const float*)d_in[11];
    const float *bih = (const float*)d_in[12], *bhh = (const float*)d_in[13];
    const float *Wg  = (const float*)d_in[14];
    const float *W1  = (const float*)d_in[15], *b1 = (const float*)d_in[16];
    const float *W2  = (const float*)d_in[17], *b2 = (const float*)d_in[18];
    const float *W3  = (const float*)d_in[19], *b3 = (const float*)d_in[20];
    float* y = (float*)d_out;

    float *qa, *qemb, *x0, *x1, *gx, *t0, *g0, *g1;
    float *xcat, *m1, *m2, *WgT, *W1T, *W2T, *bsum;
    unsigned* gbar;
    cudaGetSymbolAddress((void**)&qa,   d_qa);
    cudaGetSymbolAddress((void**)&qemb, d_qemb);
    cudaGetSymbolAddress((void**)&x0,   d_x0);
    cudaGetSymbolAddress((void**)&x1,   d_x1);
    cudaGetSymbolAddress((void**)&gx,   d_gx);
    cudaGetSymbolAddress((void**)&t0,   d_t0);
    cudaGetSymbolAddress((void**)&g0,   d_g0);
    cudaGetSymbolAddress((void**)&g1,   d_g1);
    cudaGetSymbolAddress((void**)&xcat, d_xcat);
    cudaGetSymbolAddress((void**)&m1,   d_m1);
    cudaGetSymbolAddress((void**)&m2,   d_m2);
    cudaGetSymbolAddress((void**)&WgT,  d_WgT);
    cudaGetSymbolAddress((void**)&W1T,  d_W1T);
    cudaGetSymbolAddress((void**)&W2T,  d_W2T);
    cudaGetSymbolAddress((void**)&bsum, d_bsum);
    cudaGetSymbolAddress((void**)&gbar, d_gbar);

    cudaFuncSetAttribute(lstm_layer_k, cudaFuncAttributeMaxDynamicSharedMemorySize,
                         SMEM_LSTM);

    // ---- prep: weight transposes, bias sum ----
    for (int l = 0; l < NLAY; l++)
        transpose_k<<<dim3(16, 16), dim3(32, 32)>>>(Wg + (size_t)l * HID * HID,
                                                    WgT + (size_t)l * HID * HID, HID, HID);
    transpose_k<<<dim3(16, 32), dim3(32, 32)>>>(W1, W1T, 2 * EMB, NFC1);
    transpose_k<<<dim3(8, 16),  dim3(32, 32)>>>(W2, W2T, NFC1, NFC2);
    bsum_k<<<(NLAY * G4H + 255) / 256, 256>>>(bih, bhh, bsum);

    // ---- embeddings ----
    {
        const long n = (long)LSEQ * BATCH * HID;
        embed_k<<<(unsigned)((n + 255) / 256), 256>>>(q, c, r, qsh, csh, rsh,
                                                      Wq, Wc, Wr, qa, qemb);
    }

    // ---- 5-layer LSTM: batched x-projection + persistent recurrence ----
    const float* lin = qa;
    float* lout = x0;
    for (int l = 0; l < NLAY; l++) {
        gemm_nt<128, 64, 8, 4><<<dim3(G4H / 64, (LSEQ * BATCH) / 128), 256>>>(
            lin, nullptr, 1.0f, 0.0f, HID,
            Wih + (size_t)l * G4H * HID, HID,
            gx, G4H, HID, bsum + (size_t)l * G4H, 0);
        cudaMemsetAsync(gbar, 0, sizeof(unsigned), 0);
        lstm_layer_k<<<NBLK_LSTM, 256, SMEM_LSTM>>>(gx,
            Whh + (size_t)l * G4H * HID, lout);
        lin = lout;
        lout = (lout == x0) ? x1 : x0;
    }
    const float* lstm_out = lin;

    // ---- 5 GCN layers ----
    gemm_nt<128, 64, 8, 4><<<dim3(HID / 64, (LSEQ * BATCH) / 128), 256>>>(
        lstm_out, nullptr, 1.0f, 0.0f, HID, WgT, HID, t0, HID, HID, nullptr, 0);
    adj_gemm<<<dim3((BATCH * HID) / 256, LSEQ / 25), 256>>>(adj, t0, g0, 1);
    float* gprev = g0;
    float* gnext = g1;
    for (int i = 1; i < 5; i++) {
        gemm_nt<128, 64, 8, 4><<<dim3(HID / 64, (LSEQ * BATCH) / 128), 256>>>(
            gprev, lstm_out, 1.0f - SIGMA_MIX, SIGMA_MIX, HID,
            WgT + (size_t)i * HID * HID, HID, t0, HID, HID, nullptr, 0);
        adj_gemm<<<dim3((BATCH * HID) / 256, LSEQ / 25), 256>>>(adj, t0, gnext,
                                                                (i < 4) ? 1 : 0);
        float* tmp = gprev; gprev = gnext; gnext = tmp;
    }
    const float* gfin = gprev;

    // ---- concat + MLP head ----
    {
        const long n = (long)BATCH * SEQ * (2 * EMB);
        concat_k<<<(unsigned)((n + 255) / 256), 256>>>(gfin, qemb, xcat);
    }
    const int M = BATCH * SEQ;   // 50944, divisible by 128
    gemm_nt<128, 64, 8, 4><<<dim3(NFC1 / 64, M / 128), 256>>>(
        xcat, nullptr, 1.0f, 0.0f, 2 * EMB, W1T, 2 * EMB, m1, NFC1, 2 * EMB, b1, 1);
    gemm_nt<128, 64, 8, 4><<<dim3(NFC2 / 64, M / 128), 256>>>(
        m1, nullptr, 1.0f, 0.0f, NFC1, W2T, NFC1, m2, NFC2, NFC1, b2, 1);
    mlp3_k<<<(M * 32 + 255) / 256, 256>>>(m2, W3, b3, y, M);
}

// round 4
// speedup vs baseline: 1.2882x; 1.2882x over previous
#include <cuda_runtime.h>
#include <cuda_bf16.h>
#include <math.h>
#include <stdint.h>

#define BATCH 256
#define SEQ 199
#define LSEQ 200
#define EMB 512
#define HID 512
#define G4H 2048
#define NLAY 5
#define NFC1 512
#define NFC2 256
#define SIGMA_MIX 0.5f

#define NBLK_LSTM 128
#define SMEM_LSTM ((512 * 64 + 16 * 64) * 4)

#define SMEM_SWIZZLE_128B(b) ((b) ^ (((b) >> 3) & 0x70))

__device__ __forceinline__ uint32_t smem_to_u32(const void* p) {
    uint32_t a;
    asm("{ .reg .u64 t; cvta.to.shared.u64 t, %1; cvt.u32.u64 %0, t; }" : "=r"(a) : "l"(p));
    return a;
}
__device__ __forceinline__ void cp_async16(uint32_t saddr, const void* gaddr) {
    asm volatile("cp.async.cg.shared.global [%0], [%1], 16;" :: "r"(saddr), "l"(gaddr));
}
#define CP_COMMIT() asm volatile("cp.async.commit_group;" ::: "memory")
#define CP_WAIT(N)  asm volatile("cp.async.wait_group %0;" :: "n"(N) : "memory")

__device__ __forceinline__ void ldmatrix_x4(uint32_t* r, uint32_t addr) {
    asm volatile("ldmatrix.sync.aligned.m8n8.x4.shared.b16 {%0,%1,%2,%3}, [%4];"
                 : "=r"(r[0]), "=r"(r[1]), "=r"(r[2]), "=r"(r[3]) : "r"(addr));
}
__device__ __forceinline__ void mma_bf16(float* d, const uint32_t* a, uint32_t b0, uint32_t b1) {
    asm volatile("mma.sync.aligned.m16n8k16.row.col.f32.bf16.bf16.f32 "
                 "{%0,%1,%2,%3}, {%4,%5,%6,%7}, {%8,%9}, {%0,%1,%2,%3};"
                 : "+f"(d[0]), "+f"(d[1]), "+f"(d[2]), "+f"(d[3])
                 : "r"(a[0]), "r"(a[1]), "r"(a[2]), "r"(a[3]), "r"(b0), "r"(b1));
}

// ---------------------------------------------------------------------------
// Static device scratch
// ---------------------------------------------------------------------------
__device__ float d_qa  [(size_t)LSEQ*BATCH*HID];
__device__ float d_qemb[(size_t)LSEQ*BATCH*HID];
__device__ float d_x0  [(size_t)LSEQ*BATCH*HID];
__device__ float d_x1  [(size_t)LSEQ*BATCH*HID];
__device__ float d_gx  [(size_t)LSEQ*BATCH*G4H];
__device__ float d_t0  [(size_t)LSEQ*BATCH*HID];
__device__ float d_g0  [(size_t)LSEQ*BATCH*HID];
__device__ float d_g1  [(size_t)LSEQ*BATCH*HID];
__device__ float d_xcat[(size_t)BATCH*SEQ*(2*EMB)];
__device__ float d_m1  [(size_t)BATCH*SEQ*NFC1];
__device__ float d_m2  [(size_t)BATCH*SEQ*NFC2];
__device__ float d_WgT [(size_t)NLAY*HID*HID];
__device__ float d_W1T [(size_t)NFC1*(2*EMB)];
__device__ float d_W2T [(size_t)NFC2*NFC1];
__device__ float d_bsum[(size_t)NLAY*G4H];
__device__ unsigned d_gbar;
__device__ __nv_bfloat16 d_ahi[(size_t)LSEQ*BATCH*1024];
__device__ __nv_bfloat16 d_alo[(size_t)LSEQ*BATCH*1024];
__device__ __nv_bfloat16 d_bhi[(size_t)G4H*HID];
__device__ __nv_bfloat16 d_blo[(size_t)G4H*HID];

__device__ __forceinline__ float sigf(float x) { return 1.0f / (1.0f + expf(-x)); }

// ---------------------------------------------------------------------------
// bf16-split NT GEMM on mma.sync: C[M,N] = act(A@B^T + bias)
// 3 passes: Ahi*Bhi + Ahi*Blo + Alo*Bhi, fp32 accum.
// Tile 128x128xBK64, cp.async double buffer, SW128 smem, ldmatrix + m16n8k16.
// 256 threads = 8 warps (4x2), warp tile 32x64.
// ---------------------------------------------------------------------------
#define MMA_SMEM 65536

__global__ __launch_bounds__(256)
void mma_gemm(const __nv_bfloat16* __restrict__ Ahi, const __nv_bfloat16* __restrict__ Alo,
              const __nv_bfloat16* __restrict__ Bhi, const __nv_bfloat16* __restrict__ Blo,
              float* __restrict__ C, int N, int K,
              const float* __restrict__ bias, int relu)
{
    extern __shared__ char smem[];
    const uint32_t smem_u = smem_to_u32(smem);
    const int tid = threadIdx.x;
    const int wid = tid >> 5, lane = tid & 31;
    const int warp_m = wid & 3, warp_n = wid >> 2;
    const long bm = (long)blockIdx.y * 128;
    const long bn = (long)blockIdx.x * 128;
    const int KT = K >> 6;
    const int TI = 3 * KT;

    float acc[2][8][4];
#pragma unroll
    for (int i = 0; i < 2; i++)
#pragma unroll
        for (int j = 0; j < 8; j++)
#pragma unroll
            for (int k = 0; k < 4; k++) acc[i][j][k] = 0.0f;

    auto issue_load = [&](int stage, int j) {
        const int p = j / KT, kt = j - p * KT;
        const __nv_bfloat16* Ap = (p < 2) ? Ahi : Alo;
        const __nv_bfloat16* Bp = (p == 1) ? Blo : Bhi;
        const long k0 = (long)kt << 6;
        const uint32_t sa = smem_u + stage * 32768;
        const uint32_t sb = sa + 16384;
#pragma unroll
        for (int c0 = 0; c0 < 4; c0++) {
            const int cid = tid + c0 * 256;          // 0..1023 16B chunks
            const int row = cid >> 3;
            const int o16 = cid & 7;
            const uint32_t sw = SMEM_SWIZZLE_128B((uint32_t)(row * 128 + o16 * 16));
            cp_async16(sa + sw, Ap + (bm + row) * (long)K + k0 + o16 * 8);
            cp_async16(sb + sw, Bp + (bn + row) * (long)K + k0 + o16 * 8);
        }
    };

    issue_load(0, 0);
    CP_COMMIT();

    for (int j = 0; j < TI; j++) {
        if (j + 1 < TI) {
            issue_load((j + 1) & 1, j + 1);
            CP_COMMIT();
            CP_WAIT(1);
        } else {
            CP_WAIT(0);
        }
        __syncthreads();

        const uint32_t sa = smem_u + (j & 1) * 32768;
        const uint32_t sb = sa + 16384;
#pragma unroll
        for (int ks = 0; ks < 4; ks++) {
            uint32_t afrag[2][4];
#pragma unroll
            for (int mt = 0; mt < 2; mt++) {
                const int row = warp_m * 32 + mt * 16 + (lane & 15);
                const int col = ks * 32 + (lane >> 4) * 16;
                ldmatrix_x4(afrag[mt], sa + SMEM_SWIZZLE_128B((uint32_t)(row * 128 + col)));
            }
            uint32_t bfrag[4][4];
#pragma unroll
            for (int nt2 = 0; nt2 < 4; nt2++) {
                const int nrow = warp_n * 64 + nt2 * 16 + ((lane >> 4) << 3) + (lane & 7);
                const int col = ks * 32 + ((lane >> 3) & 1) * 16;
                ldmatrix_x4(bfrag[nt2], sb + SMEM_SWIZZLE_128B((uint32_t)(nrow * 128 + col)));
            }
#pragma unroll
            for (int mt = 0; mt < 2; mt++)
#pragma unroll
                for (int nt = 0; nt < 8; nt++)
                    mma_bf16(acc[mt][nt], afrag[mt],
                             bfrag[nt >> 1][(nt & 1) * 2 + 0],
                             bfrag[nt >> 1][(nt & 1) * 2 + 1]);
        }
        __syncthreads();
    }

    // ---- epilogue: direct register -> gmem, fused bias/relu ----
#pragma unroll
    for (int mt = 0; mt < 2; mt++) {
        const long m0 = bm + warp_m * 32 + mt * 16 + (lane >> 2);
#pragma unroll
        for (int nt = 0; nt < 8; nt++) {
            const long nn = bn + warp_n * 64 + nt * 8 + (lane & 3) * 2;
            float bx = 0.0f, by = 0.0f;
            if (bias) { const float2 bv = *reinterpret_cast<const float2*>(&bias[nn]); bx = bv.x; by = bv.y; }
            float v0 = acc[mt][nt][0] + bx, v1 = acc[mt][nt][1] + by;
            float v2 = acc[mt][nt][2] + bx, v3 = acc[mt][nt][3] + by;
            if (relu) {
                v0 = fmaxf(v0, 0.0f); v1 = fmaxf(v1, 0.0f);
                v2 = fmaxf(v2, 0.0f); v3 = fmaxf(v3, 0.0f);
            }
            *reinterpret_cast<float2*>(&C[m0 * (long)N + nn])       = make_float2(v0, v1);
            *reinterpret_cast<float2*>(&C[(m0 + 8) * (long)N + nn]) = make_float2(v2, v3);
        }
    }
}

// ---------------------------------------------------------------------------
// fp32 -> (bf16 hi, lo) split with optional blend
// ---------------------------------------------------------------------------
__global__ void split_k(const float* __restrict__ A, const float* __restrict__ A2,
                        float alpha, float beta,
                        __nv_bfloat16* __restrict__ hi, __nv_bfloat16* __restrict__ lo,
                        long n)
{
    const long i = ((long)blockIdx.x * blockDim.x + threadIdx.x) * 4;
    if (i >= n) return;
    float4 v = *reinterpret_cast<const float4*>(A + i);
    if (A2) {
        const float4 w = *reinterpret_cast<const float4*>(A2 + i);
        v.x = alpha * v.x + beta * w.x; v.y = alpha * v.y + beta * w.y;
        v.z = alpha * v.z + beta * w.z; v.w = alpha * v.w + beta * w.w;
    }
    float a[4] = {v.x, v.y, v.z, v.w};
    __nv_bfloat16 h[4], l[4];
#pragma unroll
    for (int k = 0; k < 4; k++) {
        h[k] = __float2bfloat16(a[k]);
        l[k] = __float2bfloat16(a[k] - __bfloat162float(h[k]));
    }
    *reinterpret_cast<uint2*>(hi + i) = *reinterpret_cast<uint2*>(h);
    *reinterpret_cast<uint2*>(lo + i) = *reinterpret_cast<uint2*>(l);
}

// ---------------------------------------------------------------------------
// Persistent LSTM layer (unchanged — passing since R2)
// ---------------------------------------------------------------------------
__global__ __launch_bounds__(256)
void lstm_layer_k(const float* __restrict__ gx, const float* __restrict__ Whh,
                  float* __restrict__ out)
{
    extern __shared__ float fsmem[];
    float* Bsw = fsmem;
    float (*As)[64] = (float(*)[64])(fsmem + 512 * 64);

    const int tid = threadIdx.x;
    const int tx = tid & 15;
    const int ty = tid >> 4;
    const int bm = (blockIdx.x & 3) * 64;
    const int c0 = (blockIdx.x >> 2) * 16;

    for (int i = tid; i < 64 * 128; i += 256) {
        const int n  = i >> 7;
        const int kq = (i & 127) << 2;
        const int row = ((n & 3) << 9) + c0 + (n >> 2);
        const float4 v = *reinterpret_cast<const float4*>(&Whh[(size_t)row * HID + kq]);
        Bsw[(kq + 0) * 64 + n] = v.x;
        Bsw[(kq + 1) * 64 + n] = v.y;
        Bsw[(kq + 2) * 64 + n] = v.z;
        Bsw[(kq + 3) * 64 + n] = v.w;
    }
    __syncthreads();

    float creg[4] = {0.0f, 0.0f, 0.0f, 0.0f};
    const int lrow = tid >> 2;
    const int lkq  = (tid & 3) << 2;
    unsigned phase = 0;

    for (int t = 0; t < LSEQ; t++) {
        float acc[4][4] = {};
        if (t > 0) {
            const float* h = out + (size_t)(t - 1) * BATCH * HID;
            for (int k0 = 0; k0 < HID; k0 += 16) {
                const float4 v = __ldcg(reinterpret_cast<const float4*>(
                    &h[(size_t)(bm + lrow) * HID + k0 + lkq]));
                As[lkq + 0][lrow] = v.x;
                As[lkq + 1][lrow] = v.y;
                As[lkq + 2][lrow] = v.z;
                As[lkq + 3][lrow] = v.w;
                __syncthreads();
#pragma unroll
                for (int kk = 0; kk < 16; kk++) {
                    float a[4], b[4];
                    *(float4*)a = *(const float4*)&As[kk][ty * 4];
                    *(float4*)b = *(const float4*)&Bsw[(k0 + kk) * 64 + tx * 4];
#pragma unroll
                    for (int i = 0; i < 4; i++)
#pragma unroll
                        for (int j = 0; j < 4; j++)
                            acc[i][j] = fmaf(a[i], b[j], acc[i][j]);
                }
                __syncthreads();
            }
        }
#pragma unroll
        for (int i = 0; i < 4; i++) {
            const int b = bm + ty * 4 + i;
            const size_t gxo = ((size_t)t * BATCH + b) * G4H + c0 + tx;
            const float gi = gx[gxo]            + acc[i][0];
            const float gf = gx[gxo + HID]      + acc[i][1];
            const float gg = gx[gxo + 2 * HID]  + acc[i][2];
            const float go = gx[gxo + 3 * HID]  + acc[i][3];
            const float cv = sigf(gf) * creg[i] + sigf(gi) * tanhf(gg);
            const float hv = sigf(go) * tanhf(cv);
            creg[i] = cv;
            out[((size_t)t * BATCH + b) * HID + c0 + tx] = hv;
        }
        __syncthreads();
        if (tid == 0) {
            __threadfence();
            phase++;
            atomicAdd(&d_gbar, 1u);
            while (*(volatile unsigned*)&d_gbar < phase * (unsigned)NBLK_LSTM) {}
            __threadfence();
        }
        __syncthreads();
    }
}

// ---------------------------------------------------------------------------
// Adjacency contraction
// ---------------------------------------------------------------------------
__launch_bounds__(256)
__global__ void adj_gemm(const float* __restrict__ adj, const float* __restrict__ T,
                         float* __restrict__ C, int relu)
{
    constexpr int RB = 25;
    constexpr int N = BATCH * HID;
    __shared__ float as[RB][LSEQ];
    const int r0 = blockIdx.y * RB;
    const int n  = blockIdx.x * 256 + threadIdx.x;

    for (int i = threadIdx.x; i < RB * LSEQ; i += 256)
        as[i / LSEQ][i % LSEQ] = adj[(size_t)(r0 + i / LSEQ) * LSEQ + (i % LSEQ)];
    __syncthreads();

    float acc[RB];
#pragma unroll
    for (int r = 0; r < RB; r++) acc[r] = 0.0f;
    for (int k = 0; k < LSEQ; k++) {
        const float t = T[(size_t)k * N + n];
#pragma unroll
        for (int r = 0; r < RB; r++) acc[r] = fmaf(as[r][k], t, acc[r]);
    }
#pragma unroll
    for (int r = 0; r < RB; r++) {
        float v = acc[r];
        if (relu) v = fmaxf(v, 0.0f);
        C[(size_t)(r0 + r) * N + n] = v;
    }
}

// ---------------------------------------------------------------------------
// Embedding / misc
// ---------------------------------------------------------------------------
__global__ void embed_k(const int* __restrict__ q, const int* __restrict__ c,
                        const int* __restrict__ r, const int* __restrict__ qsh,
                        const int* __restrict__ csh, const int* __restrict__ rsh,
                        const float* __restrict__ Wq, const float* __restrict__ Wc,
                        const float* __restrict__ Wr,
                        float* __restrict__ qa, float* __restrict__ qemb)
{
    const long idx = (long)blockIdx.x * blockDim.x + threadIdx.x;
    if (idx >= (long)LSEQ * BATCH * HID) return;
    const int e = (int)(idx % HID);
    const int b = (int)((idx / HID) % BATCH);
    const int t = (int)(idx / ((long)HID * BATCH));
    const int pid = (t == 0) ? q[b * SEQ]  : qsh[b * SEQ + t - 1];
    const int cid = (t == 0) ? c[b * SEQ]  : csh[b * SEQ + t - 1];
    const int tgt = (t == 0) ? r[b * SEQ]  : rsh[b * SEQ + t - 1];
    const float qe = Wq[(size_t)pid * EMB + e] + Wc[(size_t)cid * EMB + e];
    qemb[idx] = qe;
    qa[idx]   = qe + Wr[(size_t)tgt * EMB + e];
}

__global__ void transpose_k(const float* __restrict__ in, float* __restrict__ out,
                            int R, int Ccols)
{
    __shared__ float tile[32][33];
    int x = blockIdx.x * 32 + threadIdx.x;
    int y = blockIdx.y * 32 + threadIdx.y;
    if (x < Ccols && y < R) tile[threadIdx.y][threadIdx.x] = in[(size_t)y * Ccols + x];
    __syncthreads();
    x = blockIdx.y * 32 + threadIdx.x;
    y = blockIdx.x * 32 + threadIdx.y;
    if (x < R && y < Ccols) out[(size_t)y * R + x] = tile[threadIdx.x][threadIdx.y];
}

__global__ void bsum_k(const float* __restrict__ bih, const float* __restrict__ bhh,
                       float* __restrict__ bsum)
{
    const int i = blockIdx.x * blockDim.x + threadIdx.x;
    if (i < NLAY * G4H) bsum[i] = bih[i] + bhh[i];
}

__global__ void concat_k(const float* __restrict__ hg, const float* __restrict__ qe,
                         float* __restrict__ xcat)
{
    const long idx = (long)blockIdx.x * blockDim.x + threadIdx.x;
    if (idx >= (long)BATCH * SEQ * (2 * EMB)) return;
    const int f = (int)(idx % (2 * EMB));
    const int s = (int)((idx / (2 * EMB)) % SEQ);
    const int b = (int)(idx / ((long)(2 * EMB) * SEQ));
    const size_t src = ((size_t)(s + 1) * BATCH + b) * HID;
    xcat[idx] = (f < EMB) ? hg[src + f] : qe[src + (f - EMB)];
}

__global__ void mlp3_k(const float* __restrict__ X, const float* __restrict__ W3,
                       const float* __restrict__ b3, float* __restrict__ y, int M)
{
    const int warp = (blockIdx.x * blockDim.x + threadIdx.x) >> 5;
    const int lane = threadIdx.x & 31;
    if (warp >= M) return;
    const float* xr = X + (size_t)warp * NFC2;
    float s = 0.0f;
#pragma unroll
    for (int k = lane; k < NFC2; k += 32) s = fmaf(xr[k], W3[k], s);
#pragma unroll
    for (int o = 16; o > 0; o >>= 1) s += __shfl_down_sync(0xffffffffu, s, o);
    if (lane == 0) y[warp] = 1.0f / (1.0f + expf(-(s + b3[0])));
}

// ---------------------------------------------------------------------------
// Orchestration
// ---------------------------------------------------------------------------
static inline void run_split(const float* A, const float* A2, float al, float be,
                             __nv_bfloat16* hi, __nv_bfloat16* lo, long n)
{
    split_k<<<(unsigned)(n / 4 / 256), 256>>>(A, A2, al, be, hi, lo, n);
}

extern "C" void kernel_launch(void* const* d_in, const int* in_sizes, int n_in,
                              void* d_out, int out_size)
{
    const int   *q   = (const int*)d_in[0],  *c   = (const int*)d_in[1];
    const int   *r   = (const int*)d_in[2],  *qsh = (const int*)d_in[3];
    const int   *csh = (const int*)d_in[4],  *rsh = (const int*)d_in[5];
    const float *adj = (const float*)d_in[6];
    const float *Wq  = (const float*)d_in[7], *Wc  = (const float*)d_in[8];
    const float *Wr  = (const float*)d_in[9];
    const float *Wih = (const float*)d_in[10], *Whh = (const float*)d_in[11];
    const float *bih = (const float*)d_in[12], *bhh = (const float*)d_in[13];
    const float *Wg  = (const float*)d_in[14];
    const float *W1  = (const float*)d_in[15], *b1 = (const float*)d_in[16];
    const float *W2  = (const float*)d_in[17], *b2 = (const float*)d_in[18];
    const float *W3  = (const float*)d_in[19], *b3 = (const float*)d_in[20];
    float* y = (float*)d_out;

    float *qa, *qemb, *x0, *x1, *gx, *t0, *g0, *g1;
    float *xcat, *m1, *m2, *WgT, *W1T, *W2T, *bsum;
    unsigned* gbar;
    __nv_bfloat16 *ahi, *alo, *bhi, *blo;
    cudaGetSymbolAddress((void**)&qa,   d_qa);
    cudaGetSymbolAddress((void**)&qemb, d_qemb);
    cudaGetSymbolAddress((void**)&x0,   d_x0);
    cudaGetSymbolAddress((void**)&x1,   d_x1);
    cudaGetSymbolAddress((void**)&gx,   d_gx);
    cudaGetSymbolAddress((void**)&t0,   d_t0);
    cudaGetSymbolAddress((void**)&g0,   d_g0);
    cudaGetSymbolAddress((void**)&g1,   d_g1);
    cudaGetSymbolAddress((void**)&xcat, d_xcat);
    cudaGetSymbolAddress((void**)&m1,   d_m1);
    cudaGetSymbolAddress((void**)&m2,   d_m2);
    cudaGetSymbolAddress((void**)&WgT,  d_WgT);
    cudaGetSymbolAddress((void**)&W1T,  d_W1T);
    cudaGetSymbolAddress((void**)&W2T,  d_W2T);
    cudaGetSymbolAddress((void**)&bsum, d_bsum);
    cudaGetSymbolAddress((void**)&gbar, d_gbar);
    cudaGetSymbolAddress((void**)&ahi,  d_ahi);
    cudaGetSymbolAddress((void**)&alo,  d_alo);
    cudaGetSymbolAddress((void**)&bhi,  d_bhi);
    cudaGetSymbolAddress((void**)&blo,  d_blo);

    cudaFuncSetAttribute(lstm_layer_k, cudaFuncAttributeMaxDynamicSharedMemorySize, SMEM_LSTM);
    cudaFuncSetAttribute(mma_gemm, cudaFuncAttributeMaxDynamicSharedMemorySize, MMA_SMEM);

    // ---- prep ----
    for (int l = 0; l < NLAY; l++)
        transpose_k<<<dim3(16, 16), dim3(32, 32)>>>(Wg + (size_t)l * HID * HID,
                                                    WgT + (size_t)l * HID * HID, HID, HID);
    transpose_k<<<dim3(16, 32), dim3(32, 32)>>>(W1, W1T, 2 * EMB, NFC1);
    transpose_k<<<dim3(8, 16),  dim3(32, 32)>>>(W2, W2T, NFC1, NFC2);
    bsum_k<<<(NLAY * G4H + 255) / 256, 256>>>(bih, bhh, bsum);

    {
        const long n = (long)LSEQ * BATCH * HID;
        embed_k<<<(unsigned)((n + 255) / 256), 256>>>(q, c, r, qsh, csh, rsh,
                                                      Wq, Wc, Wr, qa, qemb);
    }

    const long NE = (long)LSEQ * BATCH * HID;

    // ---- 5-layer LSTM: tensor-core x-projection + persistent recurrence ----
    const float* lin = qa;
    float* lout = x0;
    for (int l = 0; l < NLAY; l++) {
        run_split(lin, nullptr, 1.f, 0.f, ahi, alo, NE);
        run_split(Wih + (size_t)l * G4H * HID, nullptr, 1.f, 0.f, bhi, blo,
                  (long)G4H * HID);
        mma_gemm<<<dim3(G4H / 128, (LSEQ * BATCH) / 128), 256, MMA_SMEM>>>(
            ahi, alo, bhi, blo, gx, G4H, HID, bsum + (size_t)l * G4H, 0);
        cudaMemsetAsync(gbar, 0, sizeof(unsigned), 0);
        lstm_layer_k<<<NBLK_LSTM, 256, SMEM_LSTM>>>(gx, Whh + (size_t)l * G4H * HID, lout);
        lin = lout;
        lout = (lout == x0) ? x1 : x0;
    }
    const float* lstm_out = lin;

    // ---- 5 GCN layers ----
    run_split(lstm_out, nullptr, 1.f, 0.f, ahi, alo, NE);
    run_split(WgT, nullptr, 1.f, 0.f, bhi, blo, (long)HID * HID);
    mma_gemm<<<dim3(HID / 128, (LSEQ * BATCH) / 128), 256, MMA_SMEM>>>(
        ahi, alo, bhi, blo, t0, HID, HID, nullptr, 0);
    adj_gemm<<<dim3((BATCH * HID) / 256, LSEQ / 25), 256>>>(adj, t0, g0, 1);
    float* gprev = g0;
    float* gnext = g1;
    for (int i = 1; i < 5; i++) {
        run_split(gprev, lstm_out, 1.0f - SIGMA_MIX, SIGMA_MIX, ahi, alo, NE);
        run_split(WgT + (size_t)i * HID * HID, nullptr, 1.f, 0.f, bhi, blo,
                  (long)HID * HID);
        mma_gemm<<<dim3(HID / 128, (LSEQ * BATCH) / 128), 256, MMA_SMEM>>>(
            ahi, alo, bhi, blo, t0, HID, HID, nullptr, 0);
        adj_gemm<<<dim3((BATCH * HID) / 256, LSEQ / 25), 256>>>(adj, t0, gnext,
                                                                (i < 4) ? 1 : 0);
        float* tmp = gprev; gprev = gnext; gnext = tmp;
    }
    const float* gfin = gprev;

    // ---- concat + MLP head ----
    {
        const long n = (long)BATCH * SEQ * (2 * EMB);
        concat_k<<<(unsigned)((n + 255) / 256), 256>>>(gfin, qemb, xcat);
    }
    const int M = BATCH * SEQ;   // 50944 = 398*128
    run_split(xcat, nullptr, 1.f, 0.f, ahi, alo, (long)M * (2 * EMB));
    run_split(W1T, nullptr, 1.f, 0.f, bhi, blo, (long)NFC1 * (2 * EMB));
    mma_gemm<<<dim3(NFC1 / 128, M / 128), 256, MMA_SMEM>>>(
        ahi, alo, bhi, blo, m1, NFC1, 2 * EMB, b1, 1);
    run_split(m1, nullptr, 1.f, 0.f, ahi, alo, (long)M * NFC1);
    run_split(W2T, nullptr, 1.f, 0.f, bhi, blo, (long)NFC2 * NFC1);
    mma_gemm<<<dim3(NFC2 / 128, M / 128), 256, MMA_SMEM>>>(
        ahi, alo, bhi, blo, m2, NFC2, NFC1, b2, 1);
    mlp3_k<<<(M * 32 + 255) / 256, 256>>>(m2, W3, b3, y, M);
}

// round 8
// speedup vs baseline: 2.1984x; 1.7066x over previous
#include <cuda_runtime.h>
#include <cuda_fp16.h>
#include <math.h>
#include <stdint.h>

#define BATCH 256
#define SEQ 199
#define LSEQ 200
#define EMB 512
#define HID 512
#define G4H 2048
#define NLAY 5
#define NFC1 512
#define NFC2 256
#define SIGMA_MIX 0.5f

#define SMEM_SWIZZLE_128B(b) ((b) ^ (((b) >> 3) & 0x70))

__device__ __forceinline__ uint32_t smem_to_u32(const void* p) {
    uint32_t a;
    asm("{ .reg .u64 t; cvta.to.shared.u64 t, %1; cvt.u32.u64 %0, t; }" : "=r"(a) : "l"(p));
    return a;
}
__device__ __forceinline__ void cp_async16(uint32_t saddr, const void* gaddr) {
    asm volatile("cp.async.cg.shared.global [%0], [%1], 16;" :: "r"(saddr), "l"(gaddr));
}
#define CP_COMMIT() asm volatile("cp.async.commit_group;" ::: "memory")
#define CP_WAIT(N)  asm volatile("cp.async.wait_group %0;" :: "n"(N) : "memory")

__device__ __forceinline__ void ldmatrix_x4(uint32_t* r, uint32_t addr) {
    asm volatile("ldmatrix.sync.aligned.m8n8.x4.shared.b16 {%0,%1,%2,%3}, [%4];"
                 : "=r"(r[0]), "=r"(r[1]), "=r"(r[2]), "=r"(r[3]) : "r"(addr));
}
__device__ __forceinline__ void mma_f16(float* d, const uint32_t* a, uint32_t b0, uint32_t b1) {
    asm volatile("mma.sync.aligned.m16n8k16.row.col.f32.f16.f16.f32 "
                 "{%0,%1,%2,%3}, {%4,%5,%6,%7}, {%8,%9}, {%0,%1,%2,%3};"
                 : "+f"(d[0]), "+f"(d[1]), "+f"(d[2]), "+f"(d[3])
                 : "r"(a[0]), "r"(a[1]), "r"(a[2]), "r"(a[3]), "r"(b0), "r"(b1));
}

// recurrence B smem addressing: row n = 1024B; XOR only the in-segment 16B
// chunk bits (4..6) with n&7 — FIX: previous version dropped bits >=7 of kb.
__device__ __forceinline__ uint32_t baddr(int n, int kb) {
    return (uint32_t)(n * 1024 + (kb ^ ((n & 7) << 4)));
}

// ---------------------------------------------------------------------------
// Static device scratch
// ---------------------------------------------------------------------------
__device__ float d_qa  [(size_t)LSEQ*BATCH*HID];
__device__ float d_qemb[(size_t)LSEQ*BATCH*HID];
__device__ float d_x0  [(size_t)LSEQ*BATCH*HID];
__device__ float d_x1  [(size_t)LSEQ*BATCH*HID];
__device__ float d_gx  [(size_t)LSEQ*BATCH*G4H];
__device__ float d_t0  [(size_t)LSEQ*BATCH*HID];
__device__ float d_g0  [(size_t)LSEQ*BATCH*HID];
__device__ float d_g1  [(size_t)LSEQ*BATCH*HID];
__device__ float d_xcat[(size_t)BATCH*SEQ*(2*EMB)];
__device__ float d_m1  [(size_t)BATCH*SEQ*NFC1];
__device__ float d_m2  [(size_t)BATCH*SEQ*NFC2];
__device__ float d_bsum[(size_t)NLAY*G4H];
__device__ unsigned d_gsync[2];
__device__ __half d_ah  [(size_t)LSEQ*BATCH*1024];
__device__ __half d_al  [(size_t)LSEQ*BATCH*1024];
__device__ __half d_bh  [(size_t)G4H*HID];
__device__ __half d_bl  [(size_t)G4H*HID];
__device__ __half d_h0h [(size_t)BATCH*HID];
__device__ __half d_h0l [(size_t)BATCH*HID];
__device__ __half d_h1h [(size_t)BATCH*HID];
__device__ __half d_h1l [(size_t)BATCH*HID];

__device__ __forceinline__ float sigf(float x) { return 1.0f / (1.0f + expf(-x)); }

// ---------------------------------------------------------------------------
// fp16 3-pass NT GEMM: C = act(A@B^T + bias), fp32 accum.
// Passes: Ahi*Bhi + Alo*Bhi + Ahi*Blo (drop lo*lo, ~2^-22).
// Tile 128x128x64, cp.async double buffer, SW128, 8 warps, warp tile 32x64.
// ---------------------------------------------------------------------------
#define MMA_SMEM 65536

__global__ __launch_bounds__(256)
void mma_gemm(const __half* __restrict__ Ahi, const __half* __restrict__ Alo,
              const __half* __restrict__ Bhi, const __half* __restrict__ Blo,
              float* __restrict__ C, int N, int K,
              const float* __restrict__ bias, int relu)
{
    extern __shared__ char smem[];
    const uint32_t smem_u = smem_to_u32(smem);
    const int tid = threadIdx.x;
    const int wid = tid >> 5, lane = tid & 31;
    const int warp_m = wid & 3, warp_n = wid >> 2;
    const long bm = (long)blockIdx.y * 128;
    const long bn = (long)blockIdx.x * 128;
    const int KT = K >> 6;
    const int TI = 3 * KT;

    float acc[2][8][4];
#pragma unroll
    for (int i = 0; i < 2; i++)
#pragma unroll
        for (int j = 0; j < 8; j++)
#pragma unroll
            for (int k = 0; k < 4; k++) acc[i][j][k] = 0.0f;

    auto issue_load = [&](int stage, int j) {
        const int p = j / KT, kt = j - p * KT;
        const __half* Ap = (p == 1) ? Alo : Ahi;
        const __half* Bp = (p == 2) ? Blo : Bhi;
        const long k0 = (long)kt << 6;
        const uint32_t sa = smem_u + stage * 32768;
        const uint32_t sb = sa + 16384;
#pragma unroll
        for (int c0 = 0; c0 < 4; c0++) {
            const int cid = tid + c0 * 256;
            const int row = cid >> 3;
            const int o16 = cid & 7;
            const uint32_t sw = SMEM_SWIZZLE_128B((uint32_t)(row * 128 + o16 * 16));
            cp_async16(sa + sw, Ap + (bm + row) * (long)K + k0 + o16 * 8);
            cp_async16(sb + sw, Bp + (bn + row) * (long)K + k0 + o16 * 8);
        }
    };

    issue_load(0, 0);
    CP_COMMIT();

    for (int j = 0; j < TI; j++) {
        if (j + 1 < TI) {
            issue_load((j + 1) & 1, j + 1);
            CP_COMMIT();
            CP_WAIT(1);
        } else {
            CP_WAIT(0);
        }
        __syncthreads();

        const uint32_t sa = smem_u + (j & 1) * 32768;
        const uint32_t sb = sa + 16384;
#pragma unroll
        for (int ks = 0; ks < 4; ks++) {
            uint32_t afrag[2][4];
#pragma unroll
            for (int mt = 0; mt < 2; mt++) {
                const int row = warp_m * 32 + mt * 16 + (lane & 15);
                const int col = ks * 32 + (lane >> 4) * 16;
                ldmatrix_x4(afrag[mt], sa + SMEM_SWIZZLE_128B((uint32_t)(row * 128 + col)));
            }
            uint32_t bfrag[4][4];
#pragma unroll
            for (int nt2 = 0; nt2 < 4; nt2++) {
                const int nrow = warp_n * 64 + nt2 * 16 + ((lane >> 4) << 3) + (lane & 7);
                const int col = ks * 32 + ((lane >> 3) & 1) * 16;
                ldmatrix_x4(bfrag[nt2], sb + SMEM_SWIZZLE_128B((uint32_t)(nrow * 128 + col)));
            }
#pragma unroll
            for (int mt = 0; mt < 2; mt++)
#pragma unroll
                for (int nt = 0; nt < 8; nt++)
                    mma_f16(acc[mt][nt], afrag[mt],
                            bfrag[nt >> 1][(nt & 1) * 2 + 0],
                            bfrag[nt >> 1][(nt & 1) * 2 + 1]);
        }
        __syncthreads();
    }

#pragma unroll
    for (int mt = 0; mt < 2; mt++) {
        const long m0 = bm + warp_m * 32 + mt * 16 + (lane >> 2);
#pragma unroll
        for (int nt = 0; nt < 8; nt++) {
            const long nn = bn + warp_n * 64 + nt * 8 + (lane & 3) * 2;
            float bx = 0.0f, by = 0.0f;
            if (bias) { const float2 bv = *reinterpret_cast<const float2*>(&bias[nn]); bx = bv.x; by = bv.y; }
            float v0 = acc[mt][nt][0] + bx, v1 = acc[mt][nt][1] + by;
            float v2 = acc[mt][nt][2] + bx, v3 = acc[mt][nt][3] + by;
            if (relu) {
                v0 = fmaxf(v0, 0.0f); v1 = fmaxf(v1, 0.0f);
                v2 = fmaxf(v2, 0.0f); v3 = fmaxf(v3, 0.0f);
            }
            *reinterpret_cast<float2*>(&C[m0 * (long)N + nn])       = make_float2(v0, v1);
            *reinterpret_cast<float2*>(&C[(m0 + 8) * (long)N + nn]) = make_float2(v2, v3);
        }
    }
}

// ---------------------------------------------------------------------------
// Persistent tensor-core LSTM layer (3-pass fp16 split).
// 128 blocks x 128 threads. Block: batch [bm,bm+64), hidden cols [c0,c0+16)
// all 4 gates, gate-major N. Whh slice in smem fp16 hi/lo.
// ---------------------------------------------------------------------------
#define LSTM2_SMEM 163840

__global__ __launch_bounds__(128)
void lstm_layer_mma(const float* __restrict__ gx, const float* __restrict__ Whh,
                    float* __restrict__ out,
                    __half* __restrict__ h0h, __half* __restrict__ h0l,
                    __half* __restrict__ h1h, __half* __restrict__ h1l)
{
    extern __shared__ char smem[];
    const uint32_t smem_u = smem_to_u32(smem);
    const uint32_t Ast_u = smem_u + 131072;

    const int tid = threadIdx.x;
    const int wid = tid >> 5, lane = tid & 31;
    const int bm = (blockIdx.x & 3) * 64;
    const int c0 = (blockIdx.x >> 2) * 16;

    for (int i = tid; i < 64 * 512; i += 128) {
        const int n = i >> 9, k = i & 511;
        const int g = n >> 4, hl = n & 15;
        const float w = Whh[(size_t)(g * 512 + c0 + hl) * 512 + k];
        const __half h = __float2half(w);
        const __half l = __float2half(w - __half2float(h));
        const uint32_t off = baddr(n, k * 2);
        *reinterpret_cast<__half*>(smem + off) = h;
        *reinterpret_cast<__half*>(smem + 65536 + off) = l;
    }
    __syncthreads();

    float creg[8];
#pragma unroll
    for (int i = 0; i < 8; i++) creg[i] = 0.0f;
    unsigned phase = 0;

    for (int t = 0; t < LSEQ; t++) {
        float acc[8][4];
#pragma unroll
        for (int i = 0; i < 8; i++)
#pragma unroll
            for (int j = 0; j < 4; j++) acc[i][j] = 0.0f;

        if (t > 0) {
            const int rb = (t - 1) & 1;
            const __half* hhi = rb ? h1h : h0h;
            const __half* hlo = rb ? h1l : h0l;

            auto issueA = [&](int stage, int kc) {
                const uint32_t sa = Ast_u + stage * 16384;
#pragma unroll
                for (int c = 0; c < 4; c++) {
                    const int cid = tid + c * 128;
                    const int row = cid >> 3, o16 = cid & 7;
                    const uint32_t sw = SMEM_SWIZZLE_128B((uint32_t)(row * 128 + o16 * 16));
                    cp_async16(sa + sw,        hhi + (bm + row) * 512 + kc * 64 + o16 * 8);
                    cp_async16(sa + 8192 + sw, hlo + (bm + row) * 512 + kc * 64 + o16 * 8);
                }
            };
            issueA(0, 0);
            CP_COMMIT();
            for (int kc = 0; kc < 8; kc++) {
                if (kc < 7) { issueA((kc + 1) & 1, kc + 1); CP_COMMIT(); CP_WAIT(1); }
                else        { CP_WAIT(0); }
                __syncthreads();
                const uint32_t sa = Ast_u + (kc & 1) * 16384;
#pragma unroll
                for (int ks = 0; ks < 4; ks++) {
                    uint32_t ahf[4], alf[4];
                    {
                        const int row = wid * 16 + (lane & 15);
                        const int col = ks * 32 + (lane >> 4) * 16;
                        const uint32_t ad = sa + SMEM_SWIZZLE_128B((uint32_t)(row * 128 + col));
                        ldmatrix_x4(ahf, ad);
                        ldmatrix_x4(alf, ad + 8192);
                    }
                    uint32_t bhf[4][4], blf[4][4];
#pragma unroll
                    for (int g2 = 0; g2 < 4; g2++) {
                        const int n_r = g2 * 16 + ((lane >> 4) << 3) + (lane & 7);
                        const int kb = (ks * 16 + ((lane >> 3) & 1) * 8) * 2 + kc * 128;
                        const uint32_t off = baddr(n_r, kb);
                        ldmatrix_x4(bhf[g2], smem_u + off);
                        ldmatrix_x4(blf[g2], smem_u + 65536 + off);
                    }
#pragma unroll
                    for (int nt = 0; nt < 8; nt++) {
                        const uint32_t b0 = bhf[nt >> 1][(nt & 1) * 2 + 0];
                        const uint32_t b1 = bhf[nt >> 1][(nt & 1) * 2 + 1];
                        mma_f16(acc[nt], ahf, b0, b1);
                        mma_f16(acc[nt], alf, b0, b1);
                        mma_f16(acc[nt], ahf,
                                blf[nt >> 1][(nt & 1) * 2 + 0],
                                blf[nt >> 1][(nt & 1) * 2 + 1]);
                    }
                }
                __syncthreads();
            }
        }

        // ---- fused pointwise (gate-major acc: nt = g*2 + hb) ----
        {
            const int wb = t & 1;
            __half* whi = wb ? h1h : h0h;
            __half* wlo = wb ? h1l : h0l;
            float* outp = out + (size_t)t * BATCH * HID;
            const float* gxp = gx + (size_t)t * BATCH * G4H;
#pragma unroll
            for (int rh = 0; rh < 2; rh++) {
                const int b = bm + wid * 16 + (lane >> 2) + rh * 8;
                const size_t gb = (size_t)b * G4H + c0;
#pragma unroll
                for (int hb = 0; hb < 2; hb++) {
#pragma unroll
                    for (int cc = 0; cc < 2; cc++) {
                        const int hl = hb * 8 + (lane & 3) * 2 + cc;
                        const int ci = rh * 4 + hb * 2 + cc;
                        const int jj = rh * 2 + cc;
                        const float gi = gxp[gb + hl]              + acc[0 + hb][jj];
                        const float gf = gxp[gb + 512 + hl]        + acc[2 + hb][jj];
                        const float gg = gxp[gb + 1024 + hl]       + acc[4 + hb][jj];
                        const float go = gxp[gb + 1536 + hl]       + acc[6 + hb][jj];
                        const float cv = sigf(gf) * creg[ci] + sigf(gi) * tanhf(gg);
                        const float hv = sigf(go) * tanhf(cv);
                        creg[ci] = cv;
                        outp[(size_t)b * HID + c0 + hl] = hv;
                        const __half hh = __float2half(hv);
                        whi[b * HID + c0 + hl] = hh;
                        wlo[b * HID + c0 + hl] = __float2half(hv - __half2float(hh));
                    }
                }
            }
        }

        // ---- grid barrier (flag-based) ----
        __syncthreads();
        if (tid == 0) {
            __threadfence();
            const unsigned old = atomicAdd(&d_gsync[0], 1u);
            if (old == phase * 128u + 127u) {
                atomicExch(&d_gsync[1], phase + 1u);
            } else {
                while (*((volatile unsigned*)&d_gsync[1]) <= phase) {}
            }
            __threadfence();
        }
        __syncthreads();
        phase++;
    }
}

// ---------------------------------------------------------------------------
// fp32 -> fp16 hi/lo split with optional blend (A and [N,K] weights)
// ---------------------------------------------------------------------------
__global__ void split_k(const float* __restrict__ A, const float* __restrict__ A2,
                        float alpha, float beta,
                        __half* __restrict__ hi, __half* __restrict__ lo, long n)
{
    const long i = ((long)blockIdx.x * blockDim.x + threadIdx.x) * 4;
    if (i >= n) return;
    float4 v = *reinterpret_cast<const float4*>(A + i);
    if (A2) {
        const float4 w = *reinterpret_cast<const float4*>(A2 + i);
        v.x = alpha * v.x + beta * w.x; v.y = alpha * v.y + beta * w.y;
        v.z = alpha * v.z + beta * w.z; v.w = alpha * v.w + beta * w.w;
    }
    float a[4] = {v.x, v.y, v.z, v.w};
    __half h[4], l[4];
#pragma unroll
    for (int k = 0; k < 4; k++) {
        h[k] = __float2half(a[k]);
        l[k] = __float2half(a[k] - __half2float(h[k]));
    }
    *reinterpret_cast<uint2*>(hi + i) = *reinterpret_cast<uint2*>(h);
    *reinterpret_cast<uint2*>(lo + i) = *reinterpret_cast<uint2*>(l);
}

// transposing fp32 [K,N] -> fp16 hi/lo [N,K]
__global__ void splitT_k(const float* __restrict__ in,
                         __half* __restrict__ hi, __half* __restrict__ lo,
                         int K, int N)
{
    __shared__ float tile[32][33];
    int x = blockIdx.x * 32 + threadIdx.x;   // n
    int y = blockIdx.y * 32 + threadIdx.y;   // k
    if (x < N && y < K) tile[threadIdx.y][threadIdx.x] = in[(size_t)y * N + x];
    __syncthreads();
    const int n = blockIdx.x * 32 + threadIdx.y;
    const int k = blockIdx.y * 32 + threadIdx.x;
    if (n < N && k < K) {
        const float w = tile[threadIdx.x][threadIdx.y];
        const __half h = __float2half(w);
        hi[(size_t)n * K + k] = h;
        lo[(size_t)n * K + k] = __float2half(w - __half2float(h));
    }
}

// ---------------------------------------------------------------------------
// Adjacency contraction / embedding / misc
// ---------------------------------------------------------------------------
__launch_bounds__(256)
__global__ void adj_gemm(const float* __restrict__ adj, const float* __restrict__ T,
                         float* __restrict__ C, int relu)
{
    constexpr int RB = 25;
    constexpr int N = BATCH * HID;
    __shared__ float as[RB][LSEQ];
    const int r0 = blockIdx.y * RB;
    const int n  = blockIdx.x * 256 + threadIdx.x;

    for (int i = threadIdx.x; i < RB * LSEQ; i += 256)
        as[i / LSEQ][i % LSEQ] = adj[(size_t)(r0 + i / LSEQ) * LSEQ + (i % LSEQ)];
    __syncthreads();

    float acc[RB];
#pragma unroll
    for (int r = 0; r < RB; r++) acc[r] = 0.0f;
    for (int k = 0; k < LSEQ; k++) {
        const float t = T[(size_t)k * N + n];
#pragma unroll
        for (int r = 0; r < RB; r++) acc[r] = fmaf(as[r][k], t, acc[r]);
    }
#pragma unroll
    for (int r = 0; r < RB; r++) {
        float v = acc[r];
        if (relu) v = fmaxf(v, 0.0f);
        C[(size_t)(r0 + r) * N + n] = v;
    }
}

__global__ void embed_k(const int* __restrict__ q, const int* __restrict__ c,
                        const int* __restrict__ r, const int* __restrict__ qsh,
                        const int* __restrict__ csh, const int* __restrict__ rsh,
                        const float* __restrict__ Wq, const float* __restrict__ Wc,
                        const float* __restrict__ Wr,
                        float* __restrict__ qa, float* __restrict__ qemb)
{
    const long idx = (long)blockIdx.x * blockDim.x + threadIdx.x;
    if (idx >= (long)LSEQ * BATCH * HID) return;
    const int e = (int)(idx % HID);
    const int b = (int)((idx / HID) % BATCH);
    const int t = (int)(idx / ((long)HID * BATCH));
    const int pid = (t == 0) ? q[b * SEQ]  : qsh[b * SEQ + t - 1];
    const int cid = (t == 0) ? c[b * SEQ]  : csh[b * SEQ + t - 1];
    const int tgt = (t == 0) ? r[b * SEQ]  : rsh[b * SEQ + t - 1];
    const float qe = Wq[(size_t)pid * EMB + e] + Wc[(size_t)cid * EMB + e];
    qemb[idx] = qe;
    qa[idx]   = qe + Wr[(size_t)tgt * EMB + e];
}

__global__ void bsum_k(const float* __restrict__ bih, const float* __restrict__ bhh,
                       float* __restrict__ bsum)
{
    const int i = blockIdx.x * blockDim.x + threadIdx.x;
    if (i < NLAY * G4H) bsum[i] = bih[i] + bhh[i];
}

__global__ void concat_k(const float* __restrict__ hg, const float* __restrict__ qe,
                         float* __restrict__ xcat)
{
    const long idx = (long)blockIdx.x * blockDim.x + threadIdx.x;
    if (idx >= (long)BATCH * SEQ * (2 * EMB)) return;
    const int f = (int)(idx % (2 * EMB));
    const int s = (int)((idx / (2 * EMB)) % SEQ);
    const int b = (int)(idx / ((long)(2 * EMB) * SEQ));
    const size_t src = ((size_t)(s + 1) * BATCH + b) * HID;
    xcat[idx] = (f < EMB) ? hg[src + f] : qe[src + (f - EMB)];
}

__global__ void mlp3_k(const float* __restrict__ X, const float* __restrict__ W3,
                       const float* __restrict__ b3, float* __restrict__ y, int M)
{
    const int warp = (blockIdx.x * blockDim.x + threadIdx.x) >> 5;
    const int lane = threadIdx.x & 31;
    if (warp >= M) return;
    const float* xr = X + (size_t)warp * NFC2;
    float s = 0.0f;
#pragma unroll
    for (int k = lane; k < NFC2; k += 32) s = fmaf(xr[k], W3[k], s);
#pragma unroll
    for (int o = 16; o > 0; o >>= 1) s += __shfl_down_sync(0xffffffffu, s, o);
    if (lane == 0) y[warp] = 1.0f / (1.0f + expf(-(s + b3[0])));
}

// ---------------------------------------------------------------------------
// Orchestration
// ---------------------------------------------------------------------------
static inline void run_split(const float* A, const float* A2, float al, float be,
                             __half* hi, __half* lo, long n)
{
    split_k<<<(unsigned)(n / 4 / 256), 256>>>(A, A2, al, be, hi, lo, n);
}

extern "C" void kernel_launch(void* const* d_in, const int* in_sizes, int n_in,
                              void* d_out, int out_size)
{
    const int   *q   = (const int*)d_in[0],  *c   = (const int*)d_in[1];
    const int   *r   = (const int*)d_in[2],  *qsh = (const int*)d_in[3];
    const int   *csh = (const int*)d_in[4],  *rsh = (const int*)d_in[5];
    const float *adj = (const float*)d_in[6];
    const float *Wq  = (const float*)d_in[7], *Wc  = (const float*)d_in[8];
    const float *Wr  = (const float*)d_in[9];
    const float *Wih = (const float*)d_in[10], *Whh = (const float*)d_in[11];
    const float *bih = (const float*)d_in[12], *bhh = (const float*)d_in[13];
    const float *Wg  = (const float*)d_in[14];
    const float *W1  = (const float*)d_in[15], *b1 = (const float*)d_in[16];
    const float *W2  = (const float*)d_in[17], *b2 = (const float*)d_in[18];
    const float *W3  = (const float*)d_in[19], *b3 = (const float*)d_in[20];
    float* y = (float*)d_out;

    float *qa, *qemb, *x0, *x1, *gx, *t0, *g0, *g1, *xcat, *m1, *m2, *bsum;
    unsigned* gsync;
    __half *ah, *al, *bh, *bl, *h0h, *h0l, *h1h, *h1l;
    cudaGetSymbolAddress((void**)&qa,   d_qa);
    cudaGetSymbolAddress((void**)&qemb, d_qemb);
    cudaGetSymbolAddress((void**)&x0,   d_x0);
    cudaGetSymbolAddress((void**)&x1,   d_x1);
    cudaGetSymbolAddress((void**)&gx,   d_gx);
    cudaGetSymbolAddress((void**)&t0,   d_t0);
    cudaGetSymbolAddress((void**)&g0,   d_g0);
    cudaGetSymbolAddress((void**)&g1,   d_g1);
    cudaGetSymbolAddress((void**)&xcat, d_xcat);
    cudaGetSymbolAddress((void**)&m1,   d_m1);
    cudaGetSymbolAddress((void**)&m2,   d_m2);
    cudaGetSymbolAddress((void**)&bsum, d_bsum);
    cudaGetSymbolAddress((void**)&gsync, d_gsync);
    cudaGetSymbolAddress((void**)&ah,   d_ah);
    cudaGetSymbolAddress((void**)&al,   d_al);
    cudaGetSymbolAddress((void**)&bh,   d_bh);
    cudaGetSymbolAddress((void**)&bl,   d_bl);
    cudaGetSymbolAddress((void**)&h0h,  d_h0h);
    cudaGetSymbolAddress((void**)&h0l,  d_h0l);
    cudaGetSymbolAddress((void**)&h1h,  d_h1h);
    cudaGetSymbolAddress((void**)&h1l,  d_h1l);

    cudaFuncSetAttribute(mma_gemm, cudaFuncAttributeMaxDynamicSharedMemorySize, MMA_SMEM);
    cudaFuncSetAttribute(lstm_layer_mma, cudaFuncAttributeMaxDynamicSharedMemorySize, LSTM2_SMEM);

    // ---- prep ----
    bsum_k<<<(NLAY * G4H + 255) / 256, 256>>>(bih, bhh, bsum);
    {
        const long n = (long)LSEQ * BATCH * HID;
        embed_k<<<(unsigned)((n + 255) / 256), 256>>>(q, c, r, qsh, csh, rsh,
                                                      Wq, Wc, Wr, qa, qemb);
    }
    cudaMemsetAsync(gsync, 0, 8, 0);

    const long NE = (long)LSEQ * BATCH * HID;

    // ---- 5-layer LSTM ----
    const float* lin = qa;
    float* lout = x0;
    for (int l = 0; l < NLAY; l++) {
        run_split(lin, nullptr, 1.f, 0.f, ah, al, NE);
        run_split(Wih + (size_t)l * G4H * HID, nullptr, 1.f, 0.f, bh, bl,
                  (long)G4H * HID);
        mma_gemm<<<dim3(G4H / 128, (LSEQ * BATCH) / 128), 256, MMA_SMEM>>>(
            ah, al, bh, bl, gx, G4H, HID, bsum + (size_t)l * G4H, 0);
        if (l > 0) cudaMemsetAsync(gsync, 0, 8, 0);
        lstm_layer_mma<<<128, 128, LSTM2_SMEM>>>(gx, Whh + (size_t)l * G4H * HID,
                                                 lout, h0h, h0l, h1h, h1l);
        lin = lout;
        lout = (lout == x0) ? x1 : x0;
    }
    const float* lstm_out = lin;

    // ---- 5 GCN layers ----
    run_split(lstm_out, nullptr, 1.f, 0.f, ah, al, NE);
    splitT_k<<<dim3(16, 16), dim3(32, 32)>>>(Wg, bh, bl, HID, HID);
    mma_gemm<<<dim3(HID / 128, (LSEQ * BATCH) / 128), 256, MMA_SMEM>>>(
        ah, al, bh, bl, t0, HID, HID, nullptr, 0);
    adj_gemm<<<dim3((BATCH * HID) / 256, LSEQ / 25), 256>>>(adj, t0, g0, 1);
    float* gprev = g0;
    float* gnext = g1;
    for (int i = 1; i < 5; i++) {
        run_split(gprev, lstm_out, 1.0f - SIGMA_MIX, SIGMA_MIX, ah, al, NE);
        splitT_k<<<dim3(16, 16), dim3(32, 32)>>>(Wg + (size_t)i * HID * HID, bh, bl,
                                                 HID, HID);
        mma_gemm<<<dim3(HID / 128, (LSEQ * BATCH) / 128), 256, MMA_SMEM>>>(
            ah, al, bh, bl, t0, HID, HID, nullptr, 0);
        adj_gemm<<<dim3((BATCH * HID) / 256, LSEQ / 25), 256>>>(adj, t0, gnext,
                                                                (i < 4) ? 1 : 0);
        float* tmp = gprev; gprev = gnext; gnext = tmp;
    }
    const float* gfin = gprev;

    // ---- concat + MLP head ----
    {
        const long n = (long)BATCH * SEQ * (2 * EMB);
        concat_k<<<(unsigned)((n + 255) / 256), 256>>>(gfin, qemb, xcat);
    }
    const int M = BATCH * SEQ;   // 50944 = 398*128
    run_split(xcat, nullptr, 1.f, 0.f, ah, al, (long)M * (2 * EMB));
    splitT_k<<<dim3(16, 32), dim3(32, 32)>>>(W1, bh, bl, 2 * EMB, NFC1);
    mma_gemm<<<dim3(NFC1 / 128, M / 128), 256, MMA_SMEM>>>(
        ah, al, bh, bl, m1, NFC1, 2 * EMB, b1, 1);
    run_split(m1, nullptr, 1.f, 0.f, ah, al, (long)M * NFC1);
    splitT_k<<<dim3(8, 16), dim3(32, 32)>>>(W2, bh, bl, NFC1, NFC2);
    mma_gemm<<<dim3(NFC2 / 128, M / 128), 256, MMA_SMEM>>>(
        ah, al, bh, bl, m2, NFC2, NFC1, b2, 1);
    mlp3_k<<<(M * 32 + 255) / 256, 256>>>(m2, W3, b3, y, M);
}

// round 9
// speedup vs baseline: 2.4966x; 1.1356x over previous
#include <cuda_runtime.h>
#include <cuda_fp16.h>
#include <math.h>
#include <stdint.h>

#define BATCH 256
#define SEQ 199
#define LSEQ 200
#define EMB 512
#define HID 512
#define G4H 2048
#define NLAY 5
#define NFC1 512
#define NFC2 256
#define SIGMA_MIX 0.5f

#define SMEM_SWIZZLE_128B(b) ((b) ^ (((b) >> 3) & 0x70))

__device__ __forceinline__ uint32_t smem_to_u32(const void* p) {
    uint32_t a;
    asm("{ .reg .u64 t; cvta.to.shared.u64 t, %1; cvt.u32.u64 %0, t; }" : "=r"(a) : "l"(p));
    return a;
}
__device__ __forceinline__ void cp_async16(uint32_t saddr, const void* gaddr) {
    asm volatile("cp.async.cg.shared.global [%0], [%1], 16;" :: "r"(saddr), "l"(gaddr));
}
#define CP_COMMIT() asm volatile("cp.async.commit_group;" ::: "memory")
#define CP_WAIT(N)  asm volatile("cp.async.wait_group %0;" :: "n"(N) : "memory")

__device__ __forceinline__ void ldmatrix_x4(uint32_t* r, uint32_t addr) {
    asm volatile("ldmatrix.sync.aligned.m8n8.x4.shared.b16 {%0,%1,%2,%3}, [%4];"
                 : "=r"(r[0]), "=r"(r[1]), "=r"(r[2]), "=r"(r[3]) : "r"(addr));
}
__device__ __forceinline__ void mma_f16(float* d, const uint32_t* a, uint32_t b0, uint32_t b1) {
    asm volatile("mma.sync.aligned.m16n8k16.row.col.f32.f16.f16.f32 "
                 "{%0,%1,%2,%3}, {%4,%5,%6,%7}, {%8,%9}, {%0,%1,%2,%3};"
                 : "+f"(d[0]), "+f"(d[1]), "+f"(d[2]), "+f"(d[3])
                 : "r"(a[0]), "r"(a[1]), "r"(a[2]), "r"(a[3]), "r"(b0), "r"(b1));
}

// recurrence B smem addressing: row n = 1024B; XOR in-segment 16B chunk bits with n&7
__device__ __forceinline__ uint32_t baddr(int n, int kb) {
    return (uint32_t)(n * 1024 + (kb ^ ((n & 7) << 4)));
}

// ---------------------------------------------------------------------------
// Static device scratch
// ---------------------------------------------------------------------------
__device__ float d_qa  [(size_t)LSEQ*BATCH*HID];
__device__ float d_qemb[(size_t)LSEQ*BATCH*HID];
__device__ float d_x0  [(size_t)LSEQ*BATCH*HID];   // fp32 lstm out (last layer used)
__device__ float d_gx  [(size_t)LSEQ*BATCH*G4H];
__device__ float d_t0  [(size_t)LSEQ*BATCH*HID];
__device__ float d_g0  [(size_t)LSEQ*BATCH*HID];
__device__ float d_g1  [(size_t)LSEQ*BATCH*HID];
__device__ float d_xcat[(size_t)BATCH*SEQ*(2*EMB)];
__device__ float d_m1  [(size_t)BATCH*SEQ*NFC1];
__device__ float d_m2  [(size_t)BATCH*SEQ*NFC2];
__device__ float d_bsum[(size_t)NLAY*G4H];
__device__ unsigned d_gsync[2];
__device__ __half d_ah  [(size_t)LSEQ*BATCH*1024];
__device__ __half d_al  [(size_t)LSEQ*BATCH*1024];
__device__ __half d_bh  [(size_t)G4H*HID];
__device__ __half d_bl  [(size_t)G4H*HID];
__device__ __half d_hsh [(size_t)LSEQ*BATCH*HID];   // full-seq h hi
__device__ __half d_hsl [(size_t)LSEQ*BATCH*HID];   // full-seq h lo

__device__ __forceinline__ float sigf(float x) { return 1.0f / (1.0f + expf(-x)); }

// ---------------------------------------------------------------------------
// fp16 fused-3-pass NT GEMM: C = act(A@B^T + bias), fp32 accum.
// All four operand tiles resident per k-step; MMA groups:
//   Ahi*Bhi + Alo*Bhi + Ahi*Blo  (drop lo*lo)
// Tile 128x128x64, double-buffered 128KB smem, 8 warps, warp tile 32x64.
// ---------------------------------------------------------------------------
#define MMA_SMEM 131072

__global__ __launch_bounds__(256)
void mma_gemm(const __half* __restrict__ Ahi, const __half* __restrict__ Alo,
              const __half* __restrict__ Bhi, const __half* __restrict__ Blo,
              float* __restrict__ C, int N, int K,
              const float* __restrict__ bias, int relu)
{
    extern __shared__ char smem[];
    const uint32_t smem_u = smem_to_u32(smem);
    const int tid = threadIdx.x;
    const int wid = tid >> 5, lane = tid & 31;
    const int warp_m = wid & 3, warp_n = wid >> 2;
    const long bm = (long)blockIdx.y * 128;
    const long bn = (long)blockIdx.x * 128;
    const int TI = K >> 6;

    float acc[2][8][4];
#pragma unroll
    for (int i = 0; i < 2; i++)
#pragma unroll
        for (int j = 0; j < 8; j++)
#pragma unroll
            for (int k = 0; k < 4; k++) acc[i][j][k] = 0.0f;

    // stage layout: Ahi @0, Alo @16384, Bhi @32768, Blo @49152 (stage stride 65536)
    auto issue_load = [&](int stage, int kt) {
        const long k0 = (long)kt << 6;
        const uint32_t s0 = smem_u + stage * 65536;
#pragma unroll
        for (int c0 = 0; c0 < 4; c0++) {
            const int cid = tid + c0 * 256;
            const int row = cid >> 3;
            const int o16 = cid & 7;
            const uint32_t sw = SMEM_SWIZZLE_128B((uint32_t)(row * 128 + o16 * 16));
            const long aoff = (bm + row) * (long)K + k0 + o16 * 8;
            const long boff = (bn + row) * (long)K + k0 + o16 * 8;
            cp_async16(s0 + sw,         Ahi + aoff);
            cp_async16(s0 + 16384 + sw, Alo + aoff);
            cp_async16(s0 + 32768 + sw, Bhi + boff);
            cp_async16(s0 + 49152 + sw, Blo + boff);
        }
    };

    issue_load(0, 0);
    CP_COMMIT();

    for (int j = 0; j < TI; j++) {
        if (j + 1 < TI) {
            issue_load((j + 1) & 1, j + 1);
            CP_COMMIT();
            CP_WAIT(1);
        } else {
            CP_WAIT(0);
        }
        __syncthreads();

        const uint32_t s0 = smem_u + (j & 1) * 65536;
#pragma unroll
        for (int ks = 0; ks < 4; ks++) {
            uint32_t afh[2][4], afl[2][4];
#pragma unroll
            for (int mt = 0; mt < 2; mt++) {
                const int row = warp_m * 32 + mt * 16 + (lane & 15);
                const int col = ks * 32 + (lane >> 4) * 16;
                const uint32_t sw = SMEM_SWIZZLE_128B((uint32_t)(row * 128 + col));
                ldmatrix_x4(afh[mt], s0 + sw);
                ldmatrix_x4(afl[mt], s0 + 16384 + sw);
            }
            uint32_t bfh[4][4], bfl[4][4];
#pragma unroll
            for (int nt2 = 0; nt2 < 4; nt2++) {
                const int nrow = warp_n * 64 + nt2 * 16 + ((lane >> 4) << 3) + (lane & 7);
                const int col = ks * 32 + ((lane >> 3) & 1) * 16;
                const uint32_t sw = SMEM_SWIZZLE_128B((uint32_t)(nrow * 128 + col));
                ldmatrix_x4(bfh[nt2], s0 + 32768 + sw);
                ldmatrix_x4(bfl[nt2], s0 + 49152 + sw);
            }
#pragma unroll
            for (int mt = 0; mt < 2; mt++)
#pragma unroll
                for (int nt = 0; nt < 8; nt++) {
                    const uint32_t b0 = bfh[nt >> 1][(nt & 1) * 2 + 0];
                    const uint32_t b1 = bfh[nt >> 1][(nt & 1) * 2 + 1];
                    mma_f16(acc[mt][nt], afh[mt], b0, b1);
                    mma_f16(acc[mt][nt], afl[mt], b0, b1);
                    mma_f16(acc[mt][nt], afh[mt],
                            bfl[nt >> 1][(nt & 1) * 2 + 0],
                            bfl[nt >> 1][(nt & 1) * 2 + 1]);
                }
        }
        __syncthreads();
    }

#pragma unroll
    for (int mt = 0; mt < 2; mt++) {
        const long m0 = bm + warp_m * 32 + mt * 16 + (lane >> 2);
#pragma unroll
        for (int nt = 0; nt < 8; nt++) {
            const long nn = bn + warp_n * 64 + nt * 8 + (lane & 3) * 2;
            float bx = 0.0f, by = 0.0f;
            if (bias) { const float2 bv = *reinterpret_cast<const float2*>(&bias[nn]); bx = bv.x; by = bv.y; }
            float v0 = acc[mt][nt][0] + bx, v1 = acc[mt][nt][1] + by;
            float v2 = acc[mt][nt][2] + bx, v3 = acc[mt][nt][3] + by;
            if (relu) {
                v0 = fmaxf(v0, 0.0f); v1 = fmaxf(v1, 0.0f);
                v2 = fmaxf(v2, 0.0f); v3 = fmaxf(v3, 0.0f);
            }
            *reinterpret_cast<float2*>(&C[m0 * (long)N + nn])       = make_float2(v0, v1);
            *reinterpret_cast<float2*>(&C[(m0 + 8) * (long)N + nn]) = make_float2(v2, v3);
        }
    }
}

// ---------------------------------------------------------------------------
// Persistent tensor-core LSTM layer (3-pass fp16 split).
// 128 blocks x 128 threads. Writes h hi/lo into FULL-SEQUENCE buffers hseq
// (layout [t*BATCH+b, HID]) which feed the next layer's input projection.
// ---------------------------------------------------------------------------
#define LSTM2_SMEM 163840

__global__ __launch_bounds__(128)
void lstm_layer_mma(const float* __restrict__ gx, const float* __restrict__ Whh,
                    float* __restrict__ out,
                    __half* __restrict__ hsh, __half* __restrict__ hsl)
{
    extern __shared__ char smem[];
    const uint32_t smem_u = smem_to_u32(smem);
    const uint32_t Ast_u = smem_u + 131072;

    const int tid = threadIdx.x;
    const int wid = tid >> 5, lane = tid & 31;
    const int bm = (blockIdx.x & 3) * 64;
    const int c0 = (blockIdx.x >> 2) * 16;

    for (int i = tid; i < 64 * 512; i += 128) {
        const int n = i >> 9, k = i & 511;
        const int g = n >> 4, hl = n & 15;
        const float w = Whh[(size_t)(g * 512 + c0 + hl) * 512 + k];
        const __half h = __float2half(w);
        const __half l = __float2half(w - __half2float(h));
        const uint32_t off = baddr(n, k * 2);
        *reinterpret_cast<__half*>(smem + off) = h;
        *reinterpret_cast<__half*>(smem + 65536 + off) = l;
    }
    __syncthreads();

    float creg[8];
#pragma unroll
    for (int i = 0; i < 8; i++) creg[i] = 0.0f;
    unsigned phase = 0;

    for (int t = 0; t < LSEQ; t++) {
        float acc[8][4];
#pragma unroll
        for (int i = 0; i < 8; i++)
#pragma unroll
            for (int j = 0; j < 4; j++) acc[i][j] = 0.0f;

        if (t > 0) {
            const __half* hhi = hsh + (size_t)(t - 1) * BATCH * HID;
            const __half* hlo = hsl + (size_t)(t - 1) * BATCH * HID;

            auto issueA = [&](int stage, int kc) {
                const uint32_t sa = Ast_u + stage * 16384;
#pragma unroll
                for (int c = 0; c < 4; c++) {
                    const int cid = tid + c * 128;
                    const int row = cid >> 3, o16 = cid & 7;
                    const uint32_t sw = SMEM_SWIZZLE_128B((uint32_t)(row * 128 + o16 * 16));
                    cp_async16(sa + sw,        hhi + (bm + row) * 512 + kc * 64 + o16 * 8);
                    cp_async16(sa + 8192 + sw, hlo + (bm + row) * 512 + kc * 64 + o16 * 8);
                }
            };
            issueA(0, 0);
            CP_COMMIT();
            for (int kc = 0; kc < 8; kc++) {
                if (kc < 7) { issueA((kc + 1) & 1, kc + 1); CP_COMMIT(); CP_WAIT(1); }
                else        { CP_WAIT(0); }
                __syncthreads();
                const uint32_t sa = Ast_u + (kc & 1) * 16384;
#pragma unroll
                for (int ks = 0; ks < 4; ks++) {
                    uint32_t ahf[4], alf[4];
                    {
                        const int row = wid * 16 + (lane & 15);
                        const int col = ks * 32 + (lane >> 4) * 16;
                        const uint32_t ad = sa + SMEM_SWIZZLE_128B((uint32_t)(row * 128 + col));
                        ldmatrix_x4(ahf, ad);
                        ldmatrix_x4(alf, ad + 8192);
                    }
                    uint32_t bhf[4][4], blf[4][4];
#pragma unroll
                    for (int g2 = 0; g2 < 4; g2++) {
                        const int n_r = g2 * 16 + ((lane >> 4) << 3) + (lane & 7);
                        const int kb = (ks * 16 + ((lane >> 3) & 1) * 8) * 2 + kc * 128;
                        const uint32_t off = baddr(n_r, kb);
                        ldmatrix_x4(bhf[g2], smem_u + off);
                        ldmatrix_x4(blf[g2], smem_u + 65536 + off);
                    }
#pragma unroll
                    for (int nt = 0; nt < 8; nt++) {
                        const uint32_t b0 = bhf[nt >> 1][(nt & 1) * 2 + 0];
                        const uint32_t b1 = bhf[nt >> 1][(nt & 1) * 2 + 1];
                        mma_f16(acc[nt], ahf, b0, b1);
                        mma_f16(acc[nt], alf, b0, b1);
                        mma_f16(acc[nt], ahf,
                                blf[nt >> 1][(nt & 1) * 2 + 0],
                                blf[nt >> 1][(nt & 1) * 2 + 1]);
                    }
                }
                __syncthreads();
            }
        }

        // ---- fused pointwise (gate-major acc: nt = g*2 + hb) ----
        {
            __half* whi = hsh + (size_t)t * BATCH * HID;
            __half* wlo = hsl + (size_t)t * BATCH * HID;
            float* outp = out + (size_t)t * BATCH * HID;
            const float* gxp = gx + (size_t)t * BATCH * G4H;
#pragma unroll
            for (int rh = 0; rh < 2; rh++) {
                const int b = bm + wid * 16 + (lane >> 2) + rh * 8;
                const size_t gb = (size_t)b * G4H + c0;
#pragma unroll
                for (int hb = 0; hb < 2; hb++) {
#pragma unroll
                    for (int cc = 0; cc < 2; cc++) {
                        const int hl = hb * 8 + (lane & 3) * 2 + cc;
                        const int ci = rh * 4 + hb * 2 + cc;
                        const int jj = rh * 2 + cc;
                        const float gi = gxp[gb + hl]              + acc[0 + hb][jj];
                        const float gf = gxp[gb + 512 + hl]        + acc[2 + hb][jj];
                        const float gg = gxp[gb + 1024 + hl]       + acc[4 + hb][jj];
                        const float go = gxp[gb + 1536 + hl]       + acc[6 + hb][jj];
                        const float cv = sigf(gf) * creg[ci] + sigf(gi) * tanhf(gg);
                        const float hv = sigf(go) * tanhf(cv);
                        creg[ci] = cv;
                        outp[(size_t)b * HID + c0 + hl] = hv;
                        const __half hh = __float2half(hv);
                        whi[b * HID + c0 + hl] = hh;
                        wlo[b * HID + c0 + hl] = __float2half(hv - __half2float(hh));
                    }
                }
            }
        }

        // ---- grid barrier (flag-based) ----
        __syncthreads();
        if (tid == 0) {
            __threadfence();
            const unsigned old = atomicAdd(&d_gsync[0], 1u);
            if (old == phase * 128u + 127u) {
                atomicExch(&d_gsync[1], phase + 1u);
            } else {
                while (*((volatile unsigned*)&d_gsync[1]) <= phase) {}
            }
            __threadfence();
        }
        __syncthreads();
        phase++;
    }
}

// ---------------------------------------------------------------------------
// fp32 -> fp16 hi/lo split with optional blend
// ---------------------------------------------------------------------------
__global__ void split_k(const float* __restrict__ A, const float* __restrict__ A2,
                        float alpha, float beta,
                        __half* __restrict__ hi, __half* __restrict__ lo, long n)
{
    const long i = ((long)blockIdx.x * blockDim.x + threadIdx.x) * 4;
    if (i >= n) return;
    float4 v = *reinterpret_cast<const float4*>(A + i);
    if (A2) {
        const float4 w = *reinterpret_cast<const float4*>(A2 + i);
        v.x = alpha * v.x + beta * w.x; v.y = alpha * v.y + beta * w.y;
        v.z = alpha * v.z + beta * w.z; v.w = alpha * v.w + beta * w.w;
    }
    float a[4] = {v.x, v.y, v.z, v.w};
    __half h[4], l[4];
#pragma unroll
    for (int k = 0; k < 4; k++) {
        h[k] = __float2half(a[k]);
        l[k] = __float2half(a[k] - __half2float(h[k]));
    }
    *reinterpret_cast<uint2*>(hi + i) = *reinterpret_cast<uint2*>(h);
    *reinterpret_cast<uint2*>(lo + i) = *reinterpret_cast<uint2*>(l);
}

// transposing fp32 [K,N] -> fp16 hi/lo [N,K]
__global__ void splitT_k(const float* __restrict__ in,
                         __half* __restrict__ hi, __half* __restrict__ lo,
                         int K, int N)
{
    __shared__ float tile[32][33];
    int x = blockIdx.x * 32 + threadIdx.x;
    int y = blockIdx.y * 32 + threadIdx.y;
    if (x < N && y < K) tile[threadIdx.y][threadIdx.x] = in[(size_t)y * N + x];
    __syncthreads();
    const int n = blockIdx.x * 32 + threadIdx.y;
    const int k = blockIdx.y * 32 + threadIdx.x;
    if (n < N && k < K) {
        const float w = tile[threadIdx.x][threadIdx.y];
        const __half h = __float2half(w);
        hi[(size_t)n * K + k] = h;
        lo[(size_t)n * K + k] = __float2half(w - __half2float(h));
    }
}

// ---------------------------------------------------------------------------
// Adjacency contraction / embedding / misc
// ---------------------------------------------------------------------------
__launch_bounds__(256)
__global__ void adj_gemm(const float* __restrict__ adj, const float* __restrict__ T,
                         float* __restrict__ C, int relu)
{
    constexpr int RB = 25;
    constexpr int N = BATCH * HID;
    __shared__ float as[RB][LSEQ];
    const int r0 = blockIdx.y * RB;
    const int n  = blockIdx.x * 256 + threadIdx.x;

    for (int i = threadIdx.x; i < RB * LSEQ; i += 256)
        as[i / LSEQ][i % LSEQ] = adj[(size_t)(r0 + i / LSEQ) * LSEQ + (i % LSEQ)];
    __syncthreads();

    float acc[RB];
#pragma unroll
    for (int r = 0; r < RB; r++) acc[r] = 0.0f;
    for (int k = 0; k < LSEQ; k++) {
        const float t = T[(size_t)k * N + n];
#pragma unroll
        for (int r = 0; r < RB; r++) acc[r] = fmaf(as[r][k], t, acc[r]);
    }
#pragma unroll
    for (int r = 0; r < RB; r++) {
        float v = acc[r];
        if (relu) v = fmaxf(v, 0.0f);
        C[(size_t)(r0 + r) * N + n] = v;
    }
}

__global__ void embed_k(const int* __restrict__ q, const int* __restrict__ c,
                        const int* __restrict__ r, const int* __restrict__ qsh,
                        const int* __restrict__ csh, const int* __restrict__ rsh,
                        const float* __restrict__ Wq, const float* __restrict__ Wc,
                        const float* __restrict__ Wr,
                        float* __restrict__ qa, float* __restrict__ qemb)
{
    const long idx = (long)blockIdx.x * blockDim.x + threadIdx.x;
    if (idx >= (long)LSEQ * BATCH * HID) return;
    const int e = (int)(idx % HID);
    const int b = (int)((idx / HID) % BATCH);
    const int t = (int)(idx / ((long)HID * BATCH));
    const int pid = (t == 0) ? q[b * SEQ]  : qsh[b * SEQ + t - 1];
    const int cid = (t == 0) ? c[b * SEQ]  : csh[b * SEQ + t - 1];
    const int tgt = (t == 0) ? r[b * SEQ]  : rsh[b * SEQ + t - 1];
    const float qe = Wq[(size_t)pid * EMB + e] + Wc[(size_t)cid * EMB + e];
    qemb[idx] = qe;
    qa[idx]   = qe + Wr[(size_t)tgt * EMB + e];
}

__global__ void bsum_k(const float* __restrict__ bih, const float* __restrict__ bhh,
                       float* __restrict__ bsum)
{
    const int i = blockIdx.x * blockDim.x + threadIdx.x;
    if (i < NLAY * G4H) bsum[i] = bih[i] + bhh[i];
}

__global__ void concat_k(const float* __restrict__ hg, const float* __restrict__ qe,
                         float* __restrict__ xcat)
{
    const long idx = (long)blockIdx.x * blockDim.x + threadIdx.x;
    if (idx >= (long)BATCH * SEQ * (2 * EMB)) return;
    const int f = (int)(idx % (2 * EMB));
    const int s = (int)((idx / (2 * EMB)) % SEQ);
    const int b = (int)(idx / ((long)(2 * EMB) * SEQ));
    const size_t src = ((size_t)(s + 1) * BATCH + b) * HID;
    xcat[idx] = (f < EMB) ? hg[src + f] : qe[src + (f - EMB)];
}

__global__ void mlp3_k(const float* __restrict__ X, const float* __restrict__ W3,
                       const float* __restrict__ b3, float* __restrict__ y, int M)
{
    const int warp = (blockIdx.x * blockDim.x + threadIdx.x) >> 5;
    const int lane = threadIdx.x & 31;
    if (warp >= M) return;
    const float* xr = X + (size_t)warp * NFC2;
    float s = 0.0f;
#pragma unroll
    for (int k = lane; k < NFC2; k += 32) s = fmaf(xr[k], W3[k], s);
#pragma unroll
    for (int o = 16; o > 0; o >>= 1) s += __shfl_down_sync(0xffffffffu, s, o);
    if (lane == 0) y[warp] = 1.0f / (1.0f + expf(-(s + b3[0])));
}

// ---------------------------------------------------------------------------
// Orchestration
// ---------------------------------------------------------------------------
static inline void run_split(const float* A, const float* A2, float al, float be,
                             __half* hi, __half* lo, long n)
{
    split_k<<<(unsigned)(n / 4 / 256), 256>>>(A, A2, al, be, hi, lo, n);
}

extern "C" void kernel_launch(void* const* d_in, const int* in_sizes, int n_in,
                              void* d_out, int out_size)
{
    const int   *q   = (const int*)d_in[0],  *c   = (const int*)d_in[1];
    const int   *r   = (const int*)d_in[2],  *qsh = (const int*)d_in[3];
    const int   *csh = (const int*)d_in[4],  *rsh = (const int*)d_in[5];
    const float *adj = (const float*)d_in[6];
    const float *Wq  = (const float*)d_in[7], *Wc  = (const float*)d_in[8];
    const float *Wr  = (const float*)d_in[9];
    const float *Wih = (const float*)d_in[10], *Whh = (const float*)d_in[11];
    const float *bih = (const float*)d_in[12], *bhh = (const float*)d_in[13];
    const float *Wg  = (const float*)d_in[14];
    const float *W1  = (const float*)d_in[15], *b1 = (const float*)d_in[16];
    const float *W2  = (const float*)d_in[17], *b2 = (const float*)d_in[18];
    const float *W3  = (const float*)d_in[19], *b3 = (const float*)d_in[20];
    float* y = (float*)d_out;

    float *qa, *qemb, *x0, *gx, *t0, *g0, *g1, *xcat, *m1, *m2, *bsum;
    unsigned* gsync;
    __half *ah, *al, *bh, *bl, *hsh, *hsl;
    cudaGetSymbolAddress((void**)&qa,   d_qa);
    cudaGetSymbolAddress((void**)&qemb, d_qemb);
    cudaGetSymbolAddress((void**)&x0,   d_x0);
    cudaGetSymbolAddress((void**)&gx,   d_gx);
    cudaGetSymbolAddress((void**)&t0,   d_t0);
    cudaGetSymbolAddress((void**)&g0,   d_g0);
    cudaGetSymbolAddress((void**)&g1,   d_g1);
    cudaGetSymbolAddress((void**)&xcat, d_xcat);
    cudaGetSymbolAddress((void**)&m1,   d_m1);
    cudaGetSymbolAddress((void**)&m2,   d_m2);
    cudaGetSymbolAddress((void**)&bsum, d_bsum);
    cudaGetSymbolAddress((void**)&gsync, d_gsync);
    cudaGetSymbolAddress((void**)&ah,   d_ah);
    cudaGetSymbolAddress((void**)&al,   d_al);
    cudaGetSymbolAddress((void**)&bh,   d_bh);
    cudaGetSymbolAddress((void**)&bl,   d_bl);
    cudaGetSymbolAddress((void**)&hsh,  d_hsh);
    cudaGetSymbolAddress((void**)&hsl,  d_hsl);

    cudaFuncSetAttribute(mma_gemm, cudaFuncAttributeMaxDynamicSharedMemorySize, MMA_SMEM);
    cudaFuncSetAttribute(lstm_layer_mma, cudaFuncAttributeMaxDynamicSharedMemorySize, LSTM2_SMEM);

    // ---- prep ----
    bsum_k<<<(NLAY * G4H + 255) / 256, 256>>>(bih, bhh, bsum);
    {
        const long n = (long)LSEQ * BATCH * HID;
        embed_k<<<(unsigned)((n + 255) / 256), 256>>>(q, c, r, qsh, csh, rsh,
                                                      Wq, Wc, Wr, qa, qemb);
    }
    cudaMemsetAsync(gsync, 0, 8, 0);

    const long NE = (long)LSEQ * BATCH * HID;

    // ---- 5-layer LSTM: hseq carries hi/lo activations across layers ----
    run_split(qa, nullptr, 1.f, 0.f, hsh, hsl, NE);    // layer-0 input
    for (int l = 0; l < NLAY; l++) {
        run_split(Wih + (size_t)l * G4H * HID, nullptr, 1.f, 0.f, bh, bl,
                  (long)G4H * HID);
        mma_gemm<<<dim3(G4H / 128, (LSEQ * BATCH) / 128), 256, MMA_SMEM>>>(
            hsh, hsl, bh, bl, gx, G4H, HID, bsum + (size_t)l * G4H, 0);
        if (l > 0) cudaMemsetAsync(gsync, 0, 8, 0);
        // recurrence overwrites hseq with this layer's h (input proj already done)
        lstm_layer_mma<<<128, 128, LSTM2_SMEM>>>(gx, Whh + (size_t)l * G4H * HID,
                                                 x0, hsh, hsl);
    }
    const float* lstm_out = x0;

    // ---- 5 GCN layers (layer 0 A = hseq directly) ----
    splitT_k<<<dim3(16, 16), dim3(32, 32)>>>(Wg, bh, bl, HID, HID);
    mma_gemm<<<dim3(HID / 128, (LSEQ * BATCH) / 128), 256, MMA_SMEM>>>(
        hsh, hsl, bh, bl, t0, HID, HID, nullptr, 0);
    adj_gemm<<<dim3((BATCH * HID) / 256, LSEQ / 25), 256>>>(adj, t0, g0, 1);
    float* gprev = g0;
    float* gnext = g1;
    for (int i = 1; i < 5; i++) {
        run_split(gprev, lstm_out, 1.0f - SIGMA_MIX, SIGMA_MIX, ah, al, NE);
        splitT_k<<<dim3(16, 16), dim3(32, 32)>>>(Wg + (size_t)i * HID * HID, bh, bl,
                                                 HID, HID);
        mma_gemm<<<dim3(HID / 128, (LSEQ * BATCH) / 128), 256, MMA_SMEM>>>(
            ah, al, bh, bl, t0, HID, HID, nullptr, 0);
        adj_gemm<<<dim3((BATCH * HID) / 256, LSEQ / 25), 256>>>(adj, t0, gnext,
                                                                (i < 4) ? 1 : 0);
        float* tmp = gprev; gprev = gnext; gnext = tmp;
    }
    const float* gfin = gprev;

    // ---- concat + MLP head ----
    {
        const long n = (long)BATCH * SEQ * (2 * EMB);
        concat_k<<<(unsigned)((n + 255) / 256), 256>>>(gfin, qemb, xcat);
    }
    const int M = BATCH * SEQ;   // 50944 = 398*128
    run_split(xcat, nullptr, 1.f, 0.f, ah, al, (long)M * (2 * EMB));
    splitT_k<<<dim3(16, 32), dim3(32, 32)>>>(W1, bh, bl, 2 * EMB, NFC1);
    mma_gemm<<<dim3(NFC1 / 128, M / 128), 256, MMA_SMEM>>>(
        ah, al, bh, bl, m1, NFC1, 2 * EMB, b1, 1);
    run_split(m1, nullptr, 1.f, 0.f, ah, al, (long)M * NFC1);
    splitT_k<<<dim3(8, 16), dim3(32, 32)>>>(W2, bh, bl, NFC1, NFC2);
    mma_gemm<<<dim3(NFC2 / 128, M / 128), 256, MMA_SMEM>>>(
        ah, al, bh, bl, m2, NFC2, NFC1, b2, 1);
    mlp3_k<<<(M * 32 + 255) / 256, 256>>>(m2, W3, b3, y, M);
}